// round 7
// baseline (speedup 1.0000x reference)
#include <cuda_runtime.h>
#include <cuda_bf16.h>
#include <math.h>
#include <stdint.h>

// Problem constants (QwenGroupedQueryAttention_44100724195922)
#define BB   2
#define TT   2048
#define EE   2048
#define HH   16
#define DD   128
#define GG   4
#define NKVH 4
#define KVD  512
#define N1   3072
#define MM   4096

__device__ float g_qkv[(size_t)MM * N1];             // fp32
__device__ float g_k[(size_t)BB * NKVH * TT * DD];   // tf32 bits [b][kv][t][d]
__device__ float g_vt[(size_t)BB * NKVH * DD * TT];  // tf32 bits [b][kv][d][t]
__device__ float g_y[(size_t)MM * EE];               // tf32 bits (attn out)
__device__ float g_xt[(size_t)MM * EE];              // x as tf32 bits
__device__ float g_wat[(size_t)N1 * EE];             // Wa^T [N1][E] tf32 bits
__device__ float g_wpt[(size_t)EE * EE];             // Wp^T [E][E] tf32 bits

__device__ __forceinline__ uint32_t f2tf32(float x) {
    uint32_t r;
    asm("cvt.rna.tf32.f32 %0, %1;" : "=r"(r) : "f"(x));
    return r;
}

__device__ __forceinline__ void mma_tf32(float c[4], const uint32_t a[4],
                                         uint32_t b0, uint32_t b1) {
    asm volatile(
        "mma.sync.aligned.m16n8k8.row.col.f32.tf32.tf32.f32 "
        "{%0,%1,%2,%3}, {%4,%5,%6,%7}, {%8,%9}, {%0,%1,%2,%3};"
        : "+f"(c[0]), "+f"(c[1]), "+f"(c[2]), "+f"(c[3])
        : "r"(a[0]), "r"(a[1]), "r"(a[2]), "r"(a[3]), "r"(b0), "r"(b1));
}

__device__ __forceinline__ void cp16(uint32_t dst, const void* src) {
    asm volatile("cp.async.cg.shared.global [%0], [%1], 16;"
                 :: "r"(dst), "l"(src));
}
__device__ __forceinline__ void ldsm_x4(uint32_t* r, uint32_t a) {
    asm volatile("ldmatrix.sync.aligned.m8n8.x4.shared.b16 {%0,%1,%2,%3}, [%4];"
                 : "=r"(r[0]), "=r"(r[1]), "=r"(r[2]), "=r"(r[3]) : "r"(a));
}
__device__ __forceinline__ void ldsm_x2(uint32_t* r, uint32_t a) {
    asm volatile("ldmatrix.sync.aligned.m8n8.x2.shared.b16 {%0,%1}, [%2];"
                 : "=r"(r[0]), "=r"(r[1]) : "r"(a));
}

// ---------------------------------------------------------------------------
// Elementwise fp32 -> tf32 bits
// ---------------------------------------------------------------------------
__global__ __launch_bounds__(256)
void conv_tf32(const float* __restrict__ in, float* __restrict__ out, int n4) {
    int i = blockIdx.x * 256 + threadIdx.x;
    if (i >= n4) return;
    float4 v = ((const float4*)in)[i];
    uint4 t;
    t.x = f2tf32(v.x); t.y = f2tf32(v.y); t.z = f2tf32(v.z); t.w = f2tf32(v.w);
    ((uint4*)out)[i] = t;
}

// ---------------------------------------------------------------------------
// Transpose + tf32: W[K][N] -> Wt[N][K]
// ---------------------------------------------------------------------------
__global__ __launch_bounds__(256)
void transpose_tf32(const float* __restrict__ W, float* __restrict__ Wt,
                    int K, int N) {
    __shared__ float tile[32][33];
    int n0 = blockIdx.x * 32, k0 = blockIdx.y * 32;
    int tx = threadIdx.x, ty = threadIdx.y;  // (32, 8)
#pragma unroll
    for (int j = 0; j < 4; j++)
        tile[ty + j * 8][tx] = W[(size_t)(k0 + ty + j * 8) * N + n0 + tx];
    __syncthreads();
#pragma unroll
    for (int j = 0; j < 4; j++)
        Wt[(size_t)(n0 + ty + j * 8) * K + k0 + tx] =
            __uint_as_float(f2tf32(tile[tx][ty + j * 8]));
}

// ---------------------------------------------------------------------------
// TF32 GEMM (R4 gemm_v2, verified): C = A @ Bt^T (+bias). 128x128, BK=32.
// ---------------------------------------------------------------------------
#define STAGES 3
#define STG_BYTES 16384   // 128 rows * 32 floats * 4B

__global__ __launch_bounds__(256, 2)
void gemm_v2(const float* __restrict__ A, const float* __restrict__ Bt,
             const float* __restrict__ bias, float* __restrict__ C,
             int M, int N, int K) {
    extern __shared__ __align__(16) char smraw[];
    uint32_t sA = (uint32_t)__cvta_generic_to_shared(smraw);
    uint32_t sB = sA + STAGES * STG_BYTES;

    const int tid = threadIdx.x;
    const int lane = tid & 31;
    const int wid = tid >> 5;
    const int wm = wid >> 2;
    const int wn = wid & 3;
    const int bm = blockIdx.y * 128, bn = blockIdx.x * 128;

    float acc[4][4][4];
#pragma unroll
    for (int mi = 0; mi < 4; mi++)
#pragma unroll
        for (int ni = 0; ni < 4; ni++)
#pragma unroll
            for (int r = 0; r < 4; r++) acc[mi][ni][r] = 0.f;

    const int srow = tid >> 3;
    const int sk4 = tid & 7;

    auto stage_fn = [&](int kt, int stg) {
#pragma unroll
        for (int i = 0; i < 4; i++) {
            int row = srow + i * 32;
            uint32_t dst = sA + stg * STG_BYTES +
                           ((row * 8 + (sk4 ^ (row & 7))) << 4);
            cp16(dst, A + (size_t)(bm + row) * K + kt * 32 + sk4 * 4);
        }
#pragma unroll
        for (int i = 0; i < 4; i++) {
            int row = srow + i * 32;
            uint32_t dst = sB + stg * STG_BYTES +
                           ((row * 8 + (sk4 ^ (row & 7))) << 4);
            cp16(dst, Bt + (size_t)(bn + row) * K + kt * 32 + sk4 * 4);
        }
        asm volatile("cp.async.commit_group;");
    };

    const int nkt = K / 32;
    stage_fn(0, 0);
    if (nkt > 1) stage_fn(1, 1);

    const int mLane = wm * 64 + (lane & 15);
    const int k4A_base = (lane >> 4);
    const int nLane = wn * 32 + (lane & 7);
    const int k4B_base = ((lane >> 3) & 1);

    for (int kt = 0; kt < nkt; kt++) {
        int cur = kt % STAGES;
        asm volatile("cp.async.wait_group 1;");
        __syncthreads();
        if (kt + 2 < nkt) stage_fn(kt + 2, (kt + 2) % STAGES);

        uint32_t aBase = sA + cur * STG_BYTES;
        uint32_t bBase = sB + cur * STG_BYTES;
#pragma unroll
        for (int s = 0; s < 4; s++) {
            uint32_t af[4][4];
            int k4a = s * 2 + k4A_base;
#pragma unroll
            for (int mi = 0; mi < 4; mi++) {
                int m = mLane + mi * 16;
                ldsm_x4(af[mi], aBase + ((m * 8 + (k4a ^ (m & 7))) << 4));
            }
            uint32_t bf[4][2];
            int k4b = s * 2 + k4B_base;
#pragma unroll
            for (int ni = 0; ni < 4; ni++) {
                int n = nLane + ni * 8;
                ldsm_x2(bf[ni], bBase + ((n * 8 + (k4b ^ (n & 7))) << 4));
            }
#pragma unroll
            for (int mi = 0; mi < 4; mi++)
#pragma unroll
                for (int ni = 0; ni < 4; ni++)
                    mma_tf32(acc[mi][ni], af[mi], bf[ni][0], bf[ni][1]);
        }
        __syncthreads();
    }

    const int g4 = lane >> 2, a4 = lane & 3;
#pragma unroll
    for (int mi = 0; mi < 4; mi++) {
        int row = bm + wm * 64 + mi * 16 + g4;
#pragma unroll
        for (int ni = 0; ni < 4; ni++) {
            int col = bn + wn * 32 + ni * 8 + 2 * a4;
            float bx = 0.f, by = 0.f;
            if (bias) { bx = bias[col]; by = bias[col + 1]; }
            *(float2*)(C + (size_t)row * N + col) =
                make_float2(acc[mi][ni][0] + bx, acc[mi][ni][1] + by);
            *(float2*)(C + (size_t)(row + 8) * N + col) =
                make_float2(acc[mi][ni][2] + bx, acc[mi][ni][3] + by);
        }
    }
}

// ---------------------------------------------------------------------------
// RoPE v2: K -> Kg [b][kv][t][d] (coalesced), V -> Vt [b][kv][d][t] via smem
// transpose. Both get RoPE (per reference). grid (TT/64, BB*NKVH), 256 thr.
// ---------------------------------------------------------------------------
__global__ __launch_bounds__(256)
void rope_split_v2(const float* __restrict__ qkv,
                   const float* __restrict__ fc,
                   const float* __restrict__ fs,
                   float* __restrict__ Kg, float* __restrict__ Vt) {
    __shared__ float vt_s[64][133];
    const int tid = threadIdx.x;
    const int t0 = blockIdx.x * 64;
    const int bk = blockIdx.y;
    const int b = bk / NKVH, kv = bk % NKVH;
    const int bkv = b * NKVH + kv;

#pragma unroll
    for (int it = 0; it < 8; it++) {
        int idx = tid + it * 256;
        int t = idx >> 5;
        int col4 = idx & 31;        // float4 index; covers d = col4*4..+3
        int gt = t0 + t;
        const float* row = qkv + ((size_t)(b * TT + gt)) * N1 + kv * DD;
        float4 k4 = *(const float4*)(row + EE - kv * DD + kv * DD + col4 * 4);
        // (simplify: K at offset EE + kv*DD)
        k4 = *(const float4*)(qkv + ((size_t)(b * TT + gt)) * N1 + EE + kv * DD + col4 * 4);
        float4 v4 = *(const float4*)(qkv + ((size_t)(b * TT + gt)) * N1 + EE + KVD + kv * DD + col4 * 4);
        int i0 = col4 * 2, i1 = col4 * 2 + 1;
        float c0 = fc[gt * 64 + i0], s0 = fs[gt * 64 + i0];
        float c1 = fc[gt * 64 + i1], s1 = fs[gt * 64 + i1];

        uint4 ko;
        ko.x = f2tf32(k4.x * c0 - k4.y * s0);
        ko.y = f2tf32(k4.x * s0 + k4.y * c0);
        ko.z = f2tf32(k4.z * c1 - k4.w * s1);
        ko.w = f2tf32(k4.z * s1 + k4.w * c1);
        *(uint4*)(Kg + ((size_t)bkv * TT + gt) * DD + col4 * 4) = ko;

        vt_s[t][col4 * 4 + 0] = __uint_as_float(f2tf32(v4.x * c0 - v4.y * s0));
        vt_s[t][col4 * 4 + 1] = __uint_as_float(f2tf32(v4.x * s0 + v4.y * c0));
        vt_s[t][col4 * 4 + 2] = __uint_as_float(f2tf32(v4.z * c1 - v4.w * s1));
        vt_s[t][col4 * 4 + 3] = __uint_as_float(f2tf32(v4.z * s1 + v4.w * c1));
    }
    __syncthreads();

    // write V^T coalesced: d row, 64 t values
    const int d = tid >> 1;
    const int half = tid & 1;
#pragma unroll
    for (int j = 0; j < 8; j++) {
        int t = half * 32 + j * 4;
        float4 o = make_float4(vt_s[t][d], vt_s[t + 1][d],
                               vt_s[t + 2][d], vt_s[t + 3][d]);
        *(float4*)(Vt + ((size_t)bkv * DD + d) * TT + t0 + t) = o;
    }
}

// ---------------------------------------------------------------------------
// Flash attention v2: all-ldmatrix fragments, cp.async double-buffered K/V.
// Q tile 128, KV tile 64, 8 warps. Smem planes (bytes from base):
//   Q: 4 planes [128][32f]   @ 0       (65536)
//   K: 2 stg x 4 planes [64][32f]  @ 65536  (65536)
//   V: 2 stg x 2 planes [128][32f] @ 131072 (65536)
//   P: 2 planes [128][32f]   @ 196608 (32768)   total 229376 B
// ---------------------------------------------------------------------------
#define AQB 0
#define AKB 65536
#define AVB 131072
#define APB 196608
#define A_SMEM 229376

__global__ __launch_bounds__(256, 1)
void attn_v2(const float* __restrict__ qkv,
             const float* __restrict__ Kg,
             const float* __restrict__ Vt,
             float* __restrict__ Y) {
    extern __shared__ __align__(16) char smraw[];
    char* smc = smraw;
    const uint32_t sb = (uint32_t)__cvta_generic_to_shared(smraw);

    const int tid = threadIdx.x;
    const int lane = tid & 31;
    const int warp = tid >> 5;
    const int g4 = lane >> 2;
    const int a4 = lane & 3;

    const int qtile = (gridDim.x - 1) - blockIdx.x;   // heavy first
    const int bh = blockIdx.y;
    const int b = bh >> 4, h = bh & 15;
    const int bkv = b * NKVH + (h >> 2);

    // ---- stage Q (fp32 -> tf32, swizzled planes) ----
    const float* qbase = qkv + ((size_t)(b * TT + qtile * 128)) * N1 + h * DD;
#pragma unroll
    for (int it = 0; it < 16; it++) {
        int idx = tid + it * 256;
        int row = idx >> 5;
        int col4 = idx & 31;
        float4 q = *(const float4*)(qbase + (size_t)row * N1 + col4 * 4);
        uint4 t;
        t.x = f2tf32(q.x); t.y = f2tf32(q.y);
        t.z = f2tf32(q.z); t.w = f2tf32(q.w);
        int pl = col4 >> 3, c4 = col4 & 7;
        *(uint4*)(smc + AQB + pl * 16384 + row * 128 + ((c4 ^ (row & 7)) << 4)) = t;
    }

    // ---- staging lambdas ----
    const float* kgb = Kg + (size_t)bkv * TT * DD;
    const float* vtb = Vt + (size_t)bkv * DD * TT;
    const int kt_tok = tid >> 2;          // 0..63
    const int kt_q = tid & 3;             // d4 group
    const int v_d = tid >> 1;             // 0..127
    const int v_pl = tid & 1;

    auto stage_K = [&](int jt, int st) {
        const float* src = kgb + (size_t)(jt * 64 + kt_tok) * DD;
        uint32_t dbase = sb + AKB + st * 32768;
#pragma unroll
        for (int j = 0; j < 8; j++) {
            int d4 = kt_q * 8 + j;
            int pl = d4 >> 3, d4in = d4 & 7;
            cp16(dbase + pl * 8192 + kt_tok * 128 + ((d4in ^ (kt_tok & 7)) << 4),
                 src + d4 * 4);
        }
        asm volatile("cp.async.commit_group;");
    };
    auto stage_V = [&](int jt, int st) {
        const float* src = vtb + (size_t)v_d * TT + jt * 64 + v_pl * 32;
        uint32_t dbase = sb + AVB + st * 32768 + v_pl * 16384 + v_d * 128;
#pragma unroll
        for (int j = 0; j < 8; j++)
            cp16(dbase + ((j ^ (v_d & 7)) << 4), src + j * 4);
        asm volatile("cp.async.commit_group;");
    };

    float oacc[16][4];
#pragma unroll
    for (int nt = 0; nt < 16; nt++)
#pragma unroll
        for (int r = 0; r < 4; r++) oacc[nt][r] = 0.f;
    float m0 = -1e30f, m1 = -1e30f, l0 = 0.f, l1 = 0.f;

    const float scale = 0.08838834764831845f;
    const int mLane = warp * 16 + (lane & 15);
    const int nLane = lane & 15;
    const int k4hi = lane >> 4;
    const int rloc = warp * 16 + g4;
    const int grow0 = qtile * 128 + rloc;
    const int grow1 = grow0 + 8;

    const int njt = 2 * qtile + 2;
    stage_K(0, 0);

    for (int jt = 0; jt < njt; jt++) {
        const int st = jt & 1;
        const bool more = (jt + 1 < njt);
        stage_V(jt, st);
        if (more) stage_K(jt + 1, st ^ 1);

        // K(jt) complete
        if (more) asm volatile("cp.async.wait_group 2;");
        else      asm volatile("cp.async.wait_group 1;");
        __syncthreads();

        // ---- S = Q K^T (m16 x n64 per warp) ----
        float sacc[8][4];
#pragma unroll
        for (int nt = 0; nt < 8; nt++)
#pragma unroll
            for (int r = 0; r < 4; r++) sacc[nt][r] = 0.f;

#pragma unroll
        for (int kk = 0; kk < 16; kk++) {
            int pl = kk >> 2;
            int k4 = (kk & 3) * 2 + k4hi;
            uint32_t af[4];
            ldsm_x4(af, sb + AQB + pl * 16384 + mLane * 128 +
                            ((k4 ^ (mLane & 7)) << 4));
#pragma unroll
            for (int bi = 0; bi < 4; bi++) {
                int n = bi * 16 + nLane;
                uint32_t bf[4];
                ldsm_x4(bf, sb + AKB + st * 32768 + pl * 8192 + n * 128 +
                                ((k4 ^ (n & 7)) << 4));
                mma_tf32(sacc[bi * 2 + 0], af, bf[0], bf[2]);
                mma_tf32(sacc[bi * 2 + 1], af, bf[1], bf[3]);
            }
        }

        // ---- mask + online softmax ----
        if (jt >= 2 * qtile) {
#pragma unroll
            for (int nt = 0; nt < 8; nt++) {
                int gc = jt * 64 + nt * 8 + 2 * a4;
                sacc[nt][0] = (gc     > grow0) ? -1e30f : sacc[nt][0] * scale;
                sacc[nt][1] = (gc + 1 > grow0) ? -1e30f : sacc[nt][1] * scale;
                sacc[nt][2] = (gc     > grow1) ? -1e30f : sacc[nt][2] * scale;
                sacc[nt][3] = (gc + 1 > grow1) ? -1e30f : sacc[nt][3] * scale;
            }
        } else {
#pragma unroll
            for (int nt = 0; nt < 8; nt++)
#pragma unroll
                for (int r = 0; r < 4; r++) sacc[nt][r] *= scale;
        }

        float rm0 = -1e30f, rm1 = -1e30f;
#pragma unroll
        for (int nt = 0; nt < 8; nt++) {
            rm0 = fmaxf(rm0, fmaxf(sacc[nt][0], sacc[nt][1]));
            rm1 = fmaxf(rm1, fmaxf(sacc[nt][2], sacc[nt][3]));
        }
        rm0 = fmaxf(rm0, __shfl_xor_sync(0xffffffffu, rm0, 1));
        rm0 = fmaxf(rm0, __shfl_xor_sync(0xffffffffu, rm0, 2));
        rm1 = fmaxf(rm1, __shfl_xor_sync(0xffffffffu, rm1, 1));
        rm1 = fmaxf(rm1, __shfl_xor_sync(0xffffffffu, rm1, 2));

        float mn0 = fmaxf(m0, rm0), mn1 = fmaxf(m1, rm1);
        float corr0 = __expf(m0 - mn0), corr1 = __expf(m1 - mn1);
        m0 = mn0; m1 = mn1;

        float rs0 = 0.f, rs1 = 0.f;
#pragma unroll
        for (int nt = 0; nt < 8; nt++) {
            float p0 = __expf(sacc[nt][0] - mn0);
            float p1 = __expf(sacc[nt][1] - mn0);
            float p2 = __expf(sacc[nt][2] - mn1);
            float p3 = __expf(sacc[nt][3] - mn1);
            rs0 += p0 + p1; rs1 += p2 + p3;
            int cc = nt * 8 + 2 * a4;
            int pl = cc >> 5, c32 = cc & 31;
            int c4 = c32 >> 2, off = (c32 & 3) * 4;
            *(uint2*)(smc + APB + pl * 16384 + rloc * 128 +
                      ((c4 ^ (rloc & 7)) << 4) + off) =
                make_uint2(f2tf32(p0), f2tf32(p1));
            *(uint2*)(smc + APB + pl * 16384 + (rloc + 8) * 128 +
                      ((c4 ^ ((rloc + 8) & 7)) << 4) + off) =
                make_uint2(f2tf32(p2), f2tf32(p3));
        }
        rs0 += __shfl_xor_sync(0xffffffffu, rs0, 1);
        rs0 += __shfl_xor_sync(0xffffffffu, rs0, 2);
        rs1 += __shfl_xor_sync(0xffffffffu, rs1, 1);
        rs1 += __shfl_xor_sync(0xffffffffu, rs1, 2);
        l0 = l0 * corr0 + rs0;
        l1 = l1 * corr1 + rs1;

#pragma unroll
        for (int nt = 0; nt < 16; nt++) {
            oacc[nt][0] *= corr0; oacc[nt][1] *= corr0;
            oacc[nt][2] *= corr1; oacc[nt][3] *= corr1;
        }

        // V(jt) complete + P visible
        if (more) asm volatile("cp.async.wait_group 1;");
        else      asm volatile("cp.async.wait_group 0;");
        __syncthreads();

        // ---- O += P V^T-mma (m16 x n128, k=64) ----
#pragma unroll
        for (int kk = 0; kk < 8; kk++) {
            int pl = kk >> 2;
            int k4 = (kk & 3) * 2 + k4hi;
            uint32_t af[4];
            ldsm_x4(af, sb + APB + pl * 16384 + mLane * 128 +
                            ((k4 ^ (mLane & 7)) << 4));
#pragma unroll
            for (int bi = 0; bi < 8; bi++) {
                int n = bi * 16 + nLane;
                uint32_t bf[4];
                ldsm_x4(bf, sb + AVB + st * 32768 + pl * 16384 + n * 128 +
                                ((k4 ^ (n & 7)) << 4));
                mma_tf32(oacc[bi * 2 + 0], af, bf[0], bf[2]);
                mma_tf32(oacc[bi * 2 + 1], af, bf[1], bf[3]);
            }
        }
    }

    // ---- finalize ----
    float inv0 = 1.f / l0, inv1 = 1.f / l1;
    int t0 = qtile * 128 + rloc;
    float* y0 = Y + ((size_t)(b * TT + t0)) * EE + h * DD;
    float* y1 = Y + ((size_t)(b * TT + t0 + 8)) * EE + h * DD;
#pragma unroll
    for (int nt = 0; nt < 16; nt++) {
        int cc = nt * 8 + 2 * a4;
        *(float2*)(y0 + cc) = make_float2(
            __uint_as_float(f2tf32(oacc[nt][0] * inv0)),
            __uint_as_float(f2tf32(oacc[nt][1] * inv0)));
        *(float2*)(y1 + cc) = make_float2(
            __uint_as_float(f2tf32(oacc[nt][2] * inv1)),
            __uint_as_float(f2tf32(oacc[nt][3] * inv1)));
    }
}

// ---------------------------------------------------------------------------
extern "C" void kernel_launch(void* const* d_in, const int* in_sizes, int n_in,
                              void* d_out, int out_size) {
    const float* x  = (const float*)d_in[0];
    const float* Wa = (const float*)d_in[1];
    const float* ba = (const float*)d_in[2];
    const float* Wp = (const float*)d_in[3];
    const float* fc = (const float*)d_in[4];
    const float* fs = (const float*)d_in[5];
    float* out = (float*)d_out;

    float *qkv, *kg, *vt, *yb, *xt, *wat, *wpt;
    cudaGetSymbolAddress((void**)&qkv, g_qkv);
    cudaGetSymbolAddress((void**)&kg, g_k);
    cudaGetSymbolAddress((void**)&vt, g_vt);
    cudaGetSymbolAddress((void**)&yb, g_y);
    cudaGetSymbolAddress((void**)&xt, g_xt);
    cudaGetSymbolAddress((void**)&wat, g_wat);
    cudaGetSymbolAddress((void**)&wpt, g_wpt);

    // operand prep
    conv_tf32<<<(MM * EE / 4 + 255) / 256, 256>>>(x, xt, MM * EE / 4);
    transpose_tf32<<<dim3(N1 / 32, EE / 32), dim3(32, 8)>>>(Wa, wat, EE, N1);
    transpose_tf32<<<dim3(EE / 32, EE / 32), dim3(32, 8)>>>(Wp, wpt, EE, EE);

    int gsm = STAGES * STG_BYTES * 2;
    cudaFuncSetAttribute(gemm_v2, cudaFuncAttributeMaxDynamicSharedMemorySize, gsm);

    // 1) QKV GEMM (+bias)
    gemm_v2<<<dim3(N1 / 128, MM / 128), 256, gsm>>>(xt, wat, ba, qkv, MM, N1, EE);

    // 2) RoPE on K and V; V stored transposed
    rope_split_v2<<<dim3(TT / 64, BB * NKVH), 256>>>(qkv, fc, fs, kg, vt);

    // 3) attention
    cudaFuncSetAttribute(attn_v2, cudaFuncAttributeMaxDynamicSharedMemorySize,
                         A_SMEM);
    attn_v2<<<dim3(TT / 128, BB * HH), 256, A_SMEM>>>(qkv, kg, vt, yb);

    // 4) output projection
    gemm_v2<<<dim3(EE / 128, MM / 128), 256, gsm>>>(yb, wpt, nullptr, out, MM, EE, EE);
}

// round 8
// speedup vs baseline: 1.0212x; 1.0212x over previous
#include <cuda_runtime.h>
#include <cuda_bf16.h>
#include <math.h>
#include <stdint.h>

// Problem constants (QwenGroupedQueryAttention_44100724195922)
#define BB   2
#define TT   2048
#define EE   2048
#define HH   16
#define DD   128
#define GG   4
#define NKVH 4
#define KVD  512
#define N1   3072
#define MM   4096

__device__ float g_qkv[(size_t)MM * N1];             // fp32
__device__ float g_k[(size_t)BB * NKVH * TT * DD];   // tf32 bits
__device__ float g_v[(size_t)BB * NKVH * TT * DD];   // tf32 bits
__device__ float g_y[(size_t)MM * EE];               // tf32 bits (attn out)
__device__ float g_xt[(size_t)MM * EE];              // x as tf32 bits
__device__ float g_wat[(size_t)N1 * EE];             // Wa^T [N1][E] tf32 bits
__device__ float g_wpt[(size_t)EE * EE];             // Wp^T [E][E] tf32 bits

__device__ __forceinline__ uint32_t f2tf32(float x) {
    uint32_t r;
    asm("cvt.rna.tf32.f32 %0, %1;" : "=r"(r) : "f"(x));
    return r;
}

__device__ __forceinline__ void mma_tf32(float c[4], const uint32_t a[4],
                                         uint32_t b0, uint32_t b1) {
    asm volatile(
        "mma.sync.aligned.m16n8k8.row.col.f32.tf32.tf32.f32 "
        "{%0,%1,%2,%3}, {%4,%5,%6,%7}, {%8,%9}, {%0,%1,%2,%3};"
        : "+f"(c[0]), "+f"(c[1]), "+f"(c[2]), "+f"(c[3])
        : "r"(a[0]), "r"(a[1]), "r"(a[2]), "r"(a[3]), "r"(b0), "r"(b1));
}

__device__ __forceinline__ void cp16(uint32_t dst, const void* src) {
    asm volatile("cp.async.cg.shared.global [%0], [%1], 16;"
                 :: "r"(dst), "l"(src));
}
__device__ __forceinline__ void ldsm_x4(uint32_t* r, uint32_t a) {
    asm volatile("ldmatrix.sync.aligned.m8n8.x4.shared.b16 {%0,%1,%2,%3}, [%4];"
                 : "=r"(r[0]), "=r"(r[1]), "=r"(r[2]), "=r"(r[3]) : "r"(a));
}

// ---------------------------------------------------------------------------
// Elementwise fp32 -> tf32 bits
// ---------------------------------------------------------------------------
__global__ __launch_bounds__(256)
void conv_tf32(const float* __restrict__ in, float* __restrict__ out, int n4) {
    int i = blockIdx.x * 256 + threadIdx.x;
    if (i >= n4) return;
    float4 v = ((const float4*)in)[i];
    uint4 t;
    t.x = f2tf32(v.x); t.y = f2tf32(v.y); t.z = f2tf32(v.z); t.w = f2tf32(v.w);
    ((uint4*)out)[i] = t;
}

// ---------------------------------------------------------------------------
// Transpose + tf32: W[K][N] -> Wt[N][K]
// ---------------------------------------------------------------------------
__global__ __launch_bounds__(256)
void transpose_tf32(const float* __restrict__ W, float* __restrict__ Wt,
                    int K, int N) {
    __shared__ float tile[32][33];
    int n0 = blockIdx.x * 32, k0 = blockIdx.y * 32;
    int tx = threadIdx.x, ty = threadIdx.y;  // (32, 8)
#pragma unroll
    for (int j = 0; j < 4; j++)
        tile[ty + j * 8][tx] = W[(size_t)(k0 + ty + j * 8) * N + n0 + tx];
    __syncthreads();
#pragma unroll
    for (int j = 0; j < 4; j++)
        Wt[(size_t)(n0 + ty + j * 8) * K + k0 + tx] =
            __uint_as_float(f2tf32(tile[tx][ty + j * 8]));
}

// ---------------------------------------------------------------------------
// TF32 GEMM v2b: C[M,N] = A[M,K] @ Bt[N,K]^T (+bias)
// 128x128 tile, BK=32, 3-stage cp.async, ldmatrix.x4 for BOTH operands.
// Identical geometry/occupancy to gemm_v2 (2 CTAs/SM); only B-fragment
// loads changed from 4x ldsm_x2 to 2x ldsm_x4 per phase.
// ---------------------------------------------------------------------------
#define STAGES 3
#define STG_BYTES 16384   // 128 rows * 32 floats * 4B

__global__ __launch_bounds__(256, 2)
void gemm_v2b(const float* __restrict__ A, const float* __restrict__ Bt,
              const float* __restrict__ bias, float* __restrict__ C,
              int M, int N, int K) {
    extern __shared__ __align__(16) char smraw[];
    uint32_t sA = (uint32_t)__cvta_generic_to_shared(smraw);
    uint32_t sB = sA + STAGES * STG_BYTES;

    const int tid = threadIdx.x;
    const int lane = tid & 31;
    const int wid = tid >> 5;
    const int wm = wid >> 2;   // 0..1
    const int wn = wid & 3;    // 0..3
    const int bm = blockIdx.y * 128, bn = blockIdx.x * 128;

    float acc[4][4][4];
#pragma unroll
    for (int mi = 0; mi < 4; mi++)
#pragma unroll
        for (int ni = 0; ni < 4; ni++)
#pragma unroll
            for (int r = 0; r < 4; r++) acc[mi][ni][r] = 0.f;

    const int srow = tid >> 3;
    const int sk4 = tid & 7;

    auto stage_fn = [&](int kt, int stg) {
#pragma unroll
        for (int i = 0; i < 4; i++) {
            int row = srow + i * 32;
            uint32_t dst = sA + stg * STG_BYTES +
                           ((row * 8 + (sk4 ^ (row & 7))) << 4);
            cp16(dst, A + (size_t)(bm + row) * K + kt * 32 + sk4 * 4);
        }
#pragma unroll
        for (int i = 0; i < 4; i++) {
            int row = srow + i * 32;
            uint32_t dst = sB + stg * STG_BYTES +
                           ((row * 8 + (sk4 ^ (row & 7))) << 4);
            cp16(dst, Bt + (size_t)(bn + row) * K + kt * 32 + sk4 * 4);
        }
        asm volatile("cp.async.commit_group;");
    };

    const int nkt = K / 32;
    stage_fn(0, 0);
    if (nkt > 1) stage_fn(1, 1);

    // fragment lane addressing (x4 both operands)
    const int mLane = wm * 64 + (lane & 15);   // + mi*16
    const int nLane = wn * 32 + (lane & 15);   // + bi*16
    const int k4hi = lane >> 4;                // + s*2

    for (int kt = 0; kt < nkt; kt++) {
        int cur = kt % STAGES;
        asm volatile("cp.async.wait_group 1;");
        __syncthreads();
        if (kt + 2 < nkt) stage_fn(kt + 2, (kt + 2) % STAGES);

        uint32_t aBase = sA + cur * STG_BYTES;
        uint32_t bBase = sB + cur * STG_BYTES;
#pragma unroll
        for (int s = 0; s < 4; s++) {
            int k4 = s * 2 + k4hi;
            uint32_t af[4][4];
#pragma unroll
            for (int mi = 0; mi < 4; mi++) {
                int m = mLane + mi * 16;
                ldsm_x4(af[mi], aBase + ((m * 8 + (k4 ^ (m & 7))) << 4));
            }
            uint32_t bf[2][4];
#pragma unroll
            for (int bi = 0; bi < 2; bi++) {
                int n = nLane + bi * 16;
                ldsm_x4(bf[bi], bBase + ((n * 8 + (k4 ^ (n & 7))) << 4));
            }
#pragma unroll
            for (int mi = 0; mi < 4; mi++)
#pragma unroll
                for (int bi = 0; bi < 2; bi++) {
                    mma_tf32(acc[mi][bi * 2 + 0], af[mi], bf[bi][0], bf[bi][2]);
                    mma_tf32(acc[mi][bi * 2 + 1], af[mi], bf[bi][1], bf[bi][3]);
                }
        }
        __syncthreads();
    }

    const int g4 = lane >> 2, a4 = lane & 3;
#pragma unroll
    for (int mi = 0; mi < 4; mi++) {
        int row = bm + wm * 64 + mi * 16 + g4;
#pragma unroll
        for (int ni = 0; ni < 4; ni++) {
            int col = bn + wn * 32 + (ni >> 1) * 16 + (ni & 1) * 8 + 2 * a4;
            float bx = 0.f, by = 0.f;
            if (bias) { bx = bias[col]; by = bias[col + 1]; }
            *(float2*)(C + (size_t)row * N + col) =
                make_float2(acc[mi][ni][0] + bx, acc[mi][ni][1] + by);
            *(float2*)(C + (size_t)(row + 8) * N + col) =
                make_float2(acc[mi][ni][2] + bx, acc[mi][ni][3] + by);
        }
    }
}

// ---------------------------------------------------------------------------
// RoPE on K and V (per reference), split into [B,NKV,T,D], TF32 bits.
// ---------------------------------------------------------------------------
__global__ __launch_bounds__(64)
void rope_split_kernel(const float* __restrict__ qkv,
                       const float* __restrict__ fc,
                       const float* __restrict__ fs,
                       float* __restrict__ Kg, float* __restrict__ Vg) {
    int t = blockIdx.x;
    int bk = blockIdx.y;
    int b = bk / NKVH, kv = bk % NKVH;
    int i = threadIdx.x;

    float c = fc[t * 64 + i];
    float s = fs[t * 64 + i];
    const float* row = qkv + ((size_t)(b * TT + t)) * N1;

    float k0 = row[EE + kv * DD + 2 * i];
    float k1 = row[EE + kv * DD + 2 * i + 1];
    float v0 = row[EE + KVD + kv * DD + 2 * i];
    float v1 = row[EE + KVD + kv * DD + 2 * i + 1];

    size_t o = ((size_t)(b * NKVH + kv) * TT + t) * DD + 2 * i;
    Kg[o]     = __uint_as_float(f2tf32(k0 * c - k1 * s));
    Kg[o + 1] = __uint_as_float(f2tf32(k0 * s + k1 * c));
    Vg[o]     = __uint_as_float(f2tf32(v0 * c - v1 * s));
    Vg[o + 1] = __uint_as_float(f2tf32(v0 * s + v1 * c));
}

// ---------------------------------------------------------------------------
// TF32 tensor-core flash attention (R4 version, verified ~295us).
// ---------------------------------------------------------------------------
#define QS_S 132
#define KS_S 132
#define VS_S2 136
#define PS_S 68
#define SM_Q  0
#define SM_K  (128 * QS_S)
#define SM_V  (SM_K + 64 * KS_S)
#define SM_P  (SM_V + 64 * VS_S2)
#define SM_TOT (SM_P + 128 * PS_S)

__global__ __launch_bounds__(256, 1)
void attn_tf32(const float* __restrict__ qkv,
               const float* __restrict__ Kg,
               const float* __restrict__ Vg,
               float* __restrict__ Y) {
    extern __shared__ __align__(16) uint32_t smu[];
    uint32_t* Qs = smu + SM_Q;
    uint32_t* Ks = smu + SM_K;
    uint32_t* Vs = smu + SM_V;
    uint32_t* Ps = smu + SM_P;

    const int tid = threadIdx.x;
    const int lane = tid & 31;
    const int warp = tid >> 5;
    const int g4 = lane >> 2;
    const int a4 = lane & 3;

    const int qtile = (gridDim.x - 1) - blockIdx.x;
    const int bh = blockIdx.y;
    const int b = bh >> 4, h = bh & 15;
    const int kv = h >> 2;

    const float* qbase = qkv + ((size_t)(b * TT + qtile * 128)) * N1 + h * DD;
#pragma unroll
    for (int i = 0; i < 16; i++) {
        int idx = tid + i * 256;
        int row = idx >> 5;
        int col = (idx & 31) * 4;
        float4 q = *(const float4*)(qbase + (size_t)row * N1 + col);
        uint4 t;
        t.x = f2tf32(q.x); t.y = f2tf32(q.y);
        t.z = f2tf32(q.z); t.w = f2tf32(q.w);
        *(uint4*)(Qs + row * QS_S + col) = t;
    }

    float oacc[16][4];
#pragma unroll
    for (int nt = 0; nt < 16; nt++)
#pragma unroll
        for (int r = 0; r < 4; r++) oacc[nt][r] = 0.f;
    float m0 = -1e30f, m1 = -1e30f, l0 = 0.f, l1 = 0.f;

    const float scale = 0.08838834764831845f;
    const float* kbase = Kg + ((size_t)(b * NKVH + kv) * TT) * DD;
    const float* vbase = Vg + ((size_t)(b * NKVH + kv) * TT) * DD;

    const int rloc = warp * 16 + g4;
    const int grow0 = qtile * 128 + rloc;
    const int grow1 = grow0 + 8;

    const int njt = 2 * qtile + 2;
    for (int jt = 0; jt < njt; jt++) {
        __syncthreads();
#pragma unroll
        for (int i = 0; i < 8; i++) {
            int idx = tid + i * 256;
            int tok = idx >> 5;
            int col = (idx & 31) * 4;
            const float4* kp = (const float4*)(kbase + (size_t)(jt * 64 + tok) * DD + col);
            const float4* vp = (const float4*)(vbase + (size_t)(jt * 64 + tok) * DD + col);
            *(uint4*)(Ks + tok * KS_S + col) = *(const uint4*)kp;
            *(uint4*)(Vs + tok * VS_S2 + col) = *(const uint4*)vp;
        }
        __syncthreads();

        float sacc[8][4];
#pragma unroll
        for (int nt = 0; nt < 8; nt++)
#pragma unroll
            for (int r = 0; r < 4; r++) sacc[nt][r] = 0.f;

#pragma unroll
        for (int kt = 0; kt < 16; kt++) {
            uint32_t af[4];
            int c = kt * 8 + a4;
            af[0] = Qs[rloc * QS_S + c];
            af[1] = Qs[(rloc + 8) * QS_S + c];
            af[2] = Qs[rloc * QS_S + c + 4];
            af[3] = Qs[(rloc + 8) * QS_S + c + 4];
#pragma unroll
            for (int nt = 0; nt < 8; nt++) {
                int n = nt * 8 + g4;
                mma_tf32(sacc[nt], af, Ks[n * KS_S + kt * 8 + a4],
                         Ks[n * KS_S + kt * 8 + a4 + 4]);
            }
        }

        if (jt >= 2 * qtile) {
#pragma unroll
            for (int nt = 0; nt < 8; nt++) {
                int gc = jt * 64 + nt * 8 + 2 * a4;
                sacc[nt][0] = (gc     > grow0) ? -1e30f : sacc[nt][0] * scale;
                sacc[nt][1] = (gc + 1 > grow0) ? -1e30f : sacc[nt][1] * scale;
                sacc[nt][2] = (gc     > grow1) ? -1e30f : sacc[nt][2] * scale;
                sacc[nt][3] = (gc + 1 > grow1) ? -1e30f : sacc[nt][3] * scale;
            }
        } else {
#pragma unroll
            for (int nt = 0; nt < 8; nt++)
#pragma unroll
                for (int r = 0; r < 4; r++) sacc[nt][r] *= scale;
        }

        float rm0 = -1e30f, rm1 = -1e30f;
#pragma unroll
        for (int nt = 0; nt < 8; nt++) {
            rm0 = fmaxf(rm0, fmaxf(sacc[nt][0], sacc[nt][1]));
            rm1 = fmaxf(rm1, fmaxf(sacc[nt][2], sacc[nt][3]));
        }
        rm0 = fmaxf(rm0, __shfl_xor_sync(0xffffffffu, rm0, 1));
        rm0 = fmaxf(rm0, __shfl_xor_sync(0xffffffffu, rm0, 2));
        rm1 = fmaxf(rm1, __shfl_xor_sync(0xffffffffu, rm1, 1));
        rm1 = fmaxf(rm1, __shfl_xor_sync(0xffffffffu, rm1, 2));

        float mn0 = fmaxf(m0, rm0), mn1 = fmaxf(m1, rm1);
        float corr0 = __expf(m0 - mn0), corr1 = __expf(m1 - mn1);
        m0 = mn0; m1 = mn1;

        float rs0 = 0.f, rs1 = 0.f;
#pragma unroll
        for (int nt = 0; nt < 8; nt++) {
            float p0 = __expf(sacc[nt][0] - mn0);
            float p1 = __expf(sacc[nt][1] - mn0);
            float p2 = __expf(sacc[nt][2] - mn1);
            float p3 = __expf(sacc[nt][3] - mn1);
            rs0 += p0 + p1; rs1 += p2 + p3;
            int cc = nt * 8 + 2 * a4;
            *(uint2*)(Ps + rloc * PS_S + cc) = make_uint2(f2tf32(p0), f2tf32(p1));
            *(uint2*)(Ps + (rloc + 8) * PS_S + cc) = make_uint2(f2tf32(p2), f2tf32(p3));
        }
        rs0 += __shfl_xor_sync(0xffffffffu, rs0, 1);
        rs0 += __shfl_xor_sync(0xffffffffu, rs0, 2);
        rs1 += __shfl_xor_sync(0xffffffffu, rs1, 1);
        rs1 += __shfl_xor_sync(0xffffffffu, rs1, 2);
        l0 = l0 * corr0 + rs0;
        l1 = l1 * corr1 + rs1;

#pragma unroll
        for (int nt = 0; nt < 16; nt++) {
            oacc[nt][0] *= corr0; oacc[nt][1] *= corr0;
            oacc[nt][2] *= corr1; oacc[nt][3] *= corr1;
        }
        __syncwarp();

#pragma unroll
        for (int kt = 0; kt < 8; kt++) {
            uint32_t af[4];
            int c = kt * 8 + a4;
            af[0] = Ps[rloc * PS_S + c];
            af[1] = Ps[(rloc + 8) * PS_S + c];
            af[2] = Ps[rloc * PS_S + c + 4];
            af[3] = Ps[(rloc + 8) * PS_S + c + 4];
#pragma unroll
            for (int nt = 0; nt < 16; nt++) {
                mma_tf32(oacc[nt], af,
                         Vs[(kt * 8 + a4) * VS_S2 + nt * 8 + g4],
                         Vs[(kt * 8 + a4 + 4) * VS_S2 + nt * 8 + g4]);
            }
        }
    }

    float inv0 = 1.f / l0, inv1 = 1.f / l1;
    int t0 = qtile * 128 + rloc;
    float* y0 = Y + ((size_t)(b * TT + t0)) * EE + h * DD;
    float* y1 = Y + ((size_t)(b * TT + t0 + 8)) * EE + h * DD;
#pragma unroll
    for (int nt = 0; nt < 16; nt++) {
        int cc = nt * 8 + 2 * a4;
        *(float2*)(y0 + cc) = make_float2(
            __uint_as_float(f2tf32(oacc[nt][0] * inv0)),
            __uint_as_float(f2tf32(oacc[nt][1] * inv0)));
        *(float2*)(y1 + cc) = make_float2(
            __uint_as_float(f2tf32(oacc[nt][2] * inv1)),
            __uint_as_float(f2tf32(oacc[nt][3] * inv1)));
    }
}

// ---------------------------------------------------------------------------
extern "C" void kernel_launch(void* const* d_in, const int* in_sizes, int n_in,
                              void* d_out, int out_size) {
    const float* x  = (const float*)d_in[0];
    const float* Wa = (const float*)d_in[1];
    const float* ba = (const float*)d_in[2];
    const float* Wp = (const float*)d_in[3];
    const float* fc = (const float*)d_in[4];
    const float* fs = (const float*)d_in[5];
    float* out = (float*)d_out;

    float *qkv, *kg, *vg, *yb, *xt, *wat, *wpt;
    cudaGetSymbolAddress((void**)&qkv, g_qkv);
    cudaGetSymbolAddress((void**)&kg, g_k);
    cudaGetSymbolAddress((void**)&vg, g_v);
    cudaGetSymbolAddress((void**)&yb, g_y);
    cudaGetSymbolAddress((void**)&xt, g_xt);
    cudaGetSymbolAddress((void**)&wat, g_wat);
    cudaGetSymbolAddress((void**)&wpt, g_wpt);

    // operand prep
    conv_tf32<<<(MM * EE / 4 + 255) / 256, 256>>>(x, xt, MM * EE / 4);
    transpose_tf32<<<dim3(N1 / 32, EE / 32), dim3(32, 8)>>>(Wa, wat, EE, N1);
    transpose_tf32<<<dim3(EE / 32, EE / 32), dim3(32, 8)>>>(Wp, wpt, EE, EE);

    int gsm = STAGES * STG_BYTES * 2;
    cudaFuncSetAttribute(gemm_v2b, cudaFuncAttributeMaxDynamicSharedMemorySize, gsm);

    // 1) QKV GEMM (+bias)
    gemm_v2b<<<dim3(N1 / 128, MM / 128), 256, gsm>>>(xt, wat, ba, qkv, MM, N1, EE);

    // 2) RoPE on K and V
    rope_split_kernel<<<dim3(TT, BB * NKVH), 64>>>(qkv, fc, fs, kg, vg);

    // 3) attention
    int smem_bytes = SM_TOT * (int)sizeof(uint32_t);
    cudaFuncSetAttribute(attn_tf32, cudaFuncAttributeMaxDynamicSharedMemorySize,
                         smem_bytes);
    attn_tf32<<<dim3(TT / 128, BB * HH), 256, smem_bytes>>>(qkv, kg, vg, yb);

    // 4) output projection
    gemm_v2b<<<dim3(EE / 128, MM / 128), 256, gsm>>>(yb, wpt, nullptr, out, MM, EE, EE);
}

// round 10
// speedup vs baseline: 1.1185x; 1.0953x over previous
#include <cuda_runtime.h>
#include <cuda_bf16.h>
#include <math.h>
#include <stdint.h>

// Problem constants (QwenGroupedQueryAttention_44100724195922)
#define BB   2
#define TT   2048
#define EE   2048
#define HH   16
#define DD   128
#define GG   4
#define NKVH 4
#define KVD  512
#define N1   3072
#define MM   4096

__device__ float g_qkv[(size_t)MM * N1];             // fp32
__device__ float g_k[(size_t)BB * NKVH * TT * DD];   // tf32 bits
__device__ float g_v[(size_t)BB * NKVH * TT * DD];   // tf32 bits
__device__ float g_y[(size_t)MM * EE];               // tf32 bits (attn out)
__device__ float g_xt[(size_t)MM * EE];              // x as tf32 bits
__device__ float g_wat[(size_t)N1 * EE];             // Wa^T [N1][E] tf32 bits
__device__ float g_wpt[(size_t)EE * EE];             // Wp^T [E][E] tf32 bits

__device__ __forceinline__ uint32_t f2tf32(float x) {
    uint32_t r;
    asm("cvt.rna.tf32.f32 %0, %1;" : "=r"(r) : "f"(x));
    return r;
}

__device__ __forceinline__ void mma_tf32(float c[4], const uint32_t a[4],
                                         uint32_t b0, uint32_t b1) {
    asm volatile(
        "mma.sync.aligned.m16n8k8.row.col.f32.tf32.tf32.f32 "
        "{%0,%1,%2,%3}, {%4,%5,%6,%7}, {%8,%9}, {%0,%1,%2,%3};"
        : "+f"(c[0]), "+f"(c[1]), "+f"(c[2]), "+f"(c[3])
        : "r"(a[0]), "r"(a[1]), "r"(a[2]), "r"(a[3]), "r"(b0), "r"(b1));
}

__device__ __forceinline__ void cp16(uint32_t dst, const void* src) {
    asm volatile("cp.async.cg.shared.global [%0], [%1], 16;"
                 :: "r"(dst), "l"(src));
}
__device__ __forceinline__ void ldsm_x4(uint32_t* r, uint32_t a) {
    asm volatile("ldmatrix.sync.aligned.m8n8.x4.shared.b16 {%0,%1,%2,%3}, [%4];"
                 : "=r"(r[0]), "=r"(r[1]), "=r"(r[2]), "=r"(r[3]) : "r"(a));
}
__device__ __forceinline__ void ldsm_x2(uint32_t* r, uint32_t a) {
    asm volatile("ldmatrix.sync.aligned.m8n8.x2.shared.b16 {%0,%1}, [%2];"
                 : "=r"(r[0]), "=r"(r[1]) : "r"(a));
}

// ---------------------------------------------------------------------------
// Elementwise fp32 -> tf32 bits
// ---------------------------------------------------------------------------
__global__ __launch_bounds__(256)
void conv_tf32(const float* __restrict__ in, float* __restrict__ out, int n4) {
    int i = blockIdx.x * 256 + threadIdx.x;
    if (i >= n4) return;
    float4 v = ((const float4*)in)[i];
    uint4 t;
    t.x = f2tf32(v.x); t.y = f2tf32(v.y); t.z = f2tf32(v.z); t.w = f2tf32(v.w);
    ((uint4*)out)[i] = t;
}

// ---------------------------------------------------------------------------
// Transpose + tf32: W[K][N] -> Wt[N][K]
// ---------------------------------------------------------------------------
__global__ __launch_bounds__(256)
void transpose_tf32(const float* __restrict__ W, float* __restrict__ Wt,
                    int K, int N) {
    __shared__ float tile[32][33];
    int n0 = blockIdx.x * 32, k0 = blockIdx.y * 32;
    int tx = threadIdx.x, ty = threadIdx.y;  // (32, 8)
#pragma unroll
    for (int j = 0; j < 4; j++)
        tile[ty + j * 8][tx] = W[(size_t)(k0 + ty + j * 8) * N + n0 + tx];
    __syncthreads();
#pragma unroll
    for (int j = 0; j < 4; j++)
        Wt[(size_t)(n0 + ty + j * 8) * K + k0 + tx] =
            __uint_as_float(f2tf32(tile[tx][ty + j * 8]));
}

// ---------------------------------------------------------------------------
// TF32 GEMM (gemm_v2 with single barrier per k-iter): C = A @ Bt^T (+bias)
// 128x128 tile, BK=32, 3-stage cp.async, ldmatrix, XOR-swizzled smem.
// Safety of single barrier: a warp reaches barrier(kt) only after finishing
// compute(kt-1); so when any warp passes barrier(kt), ALL warps are done
// reading buffer (kt-1)%3 == (kt+2)%3, which stage(kt+2) then overwrites.
// ---------------------------------------------------------------------------
#define STAGES 3
#define STG_BYTES 16384   // 128 rows * 32 floats * 4B

__global__ __launch_bounds__(256, 2)
void gemm_v2(const float* __restrict__ A, const float* __restrict__ Bt,
             const float* __restrict__ bias, float* __restrict__ C,
             int M, int N, int K) {
    extern __shared__ __align__(16) char smraw[];
    uint32_t sA = (uint32_t)__cvta_generic_to_shared(smraw);
    uint32_t sB = sA + STAGES * STG_BYTES;

    const int tid = threadIdx.x;
    const int lane = tid & 31;
    const int wid = tid >> 5;
    const int wm = wid >> 2;
    const int wn = wid & 3;
    const int bm = blockIdx.y * 128, bn = blockIdx.x * 128;

    float acc[4][4][4];
#pragma unroll
    for (int mi = 0; mi < 4; mi++)
#pragma unroll
        for (int ni = 0; ni < 4; ni++)
#pragma unroll
            for (int r = 0; r < 4; r++) acc[mi][ni][r] = 0.f;

    const int srow = tid >> 3;
    const int sk4 = tid & 7;

    auto stage_fn = [&](int kt, int stg) {
#pragma unroll
        for (int i = 0; i < 4; i++) {
            int row = srow + i * 32;
            uint32_t dst = sA + stg * STG_BYTES +
                           ((row * 8 + (sk4 ^ (row & 7))) << 4);
            cp16(dst, A + (size_t)(bm + row) * K + kt * 32 + sk4 * 4);
        }
#pragma unroll
        for (int i = 0; i < 4; i++) {
            int row = srow + i * 32;
            uint32_t dst = sB + stg * STG_BYTES +
                           ((row * 8 + (sk4 ^ (row & 7))) << 4);
            cp16(dst, Bt + (size_t)(bn + row) * K + kt * 32 + sk4 * 4);
        }
        asm volatile("cp.async.commit_group;");
    };

    const int nkt = K / 32;
    stage_fn(0, 0);
    if (nkt > 1) stage_fn(1, 1);

    const int mLane = wm * 64 + (lane & 15);
    const int k4A_base = (lane >> 4);
    const int nLane = wn * 32 + (lane & 7);
    const int k4B_base = ((lane >> 3) & 1);

    for (int kt = 0; kt < nkt; kt++) {
        int cur = kt % STAGES;
        asm volatile("cp.async.wait_group 1;");
        __syncthreads();   // single barrier per iteration
        if (kt + 2 < nkt) stage_fn(kt + 2, (kt + 2) % STAGES);

        uint32_t aBase = sA + cur * STG_BYTES;
        uint32_t bBase = sB + cur * STG_BYTES;
#pragma unroll
        for (int s = 0; s < 4; s++) {
            uint32_t af[4][4];
            int k4a = s * 2 + k4A_base;
#pragma unroll
            for (int mi = 0; mi < 4; mi++) {
                int m = mLane + mi * 16;
                ldsm_x4(af[mi], aBase + ((m * 8 + (k4a ^ (m & 7))) << 4));
            }
            uint32_t bf[4][2];
            int k4b = s * 2 + k4B_base;
#pragma unroll
            for (int ni = 0; ni < 4; ni++) {
                int n = nLane + ni * 8;
                ldsm_x2(bf[ni], bBase + ((n * 8 + (k4b ^ (n & 7))) << 4));
            }
#pragma unroll
            for (int mi = 0; mi < 4; mi++)
#pragma unroll
                for (int ni = 0; ni < 4; ni++)
                    mma_tf32(acc[mi][ni], af[mi], bf[ni][0], bf[ni][1]);
        }
        // no trailing barrier (see header comment)
    }

    const int g4 = lane >> 2, a4 = lane & 3;
#pragma unroll
    for (int mi = 0; mi < 4; mi++) {
        int row = bm + wm * 64 + mi * 16 + g4;
#pragma unroll
        for (int ni = 0; ni < 4; ni++) {
            int col = bn + wn * 32 + ni * 8 + 2 * a4;
            float bx = 0.f, by = 0.f;
            if (bias) { bx = bias[col]; by = bias[col + 1]; }
            *(float2*)(C + (size_t)row * N + col) =
                make_float2(acc[mi][ni][0] + bx, acc[mi][ni][1] + by);
            *(float2*)(C + (size_t)(row + 8) * N + col) =
                make_float2(acc[mi][ni][2] + bx, acc[mi][ni][3] + by);
        }
    }
}

// ---------------------------------------------------------------------------
// RoPE on K and V (per reference), split into [B,NKV,T,D], TF32 bits.
// ---------------------------------------------------------------------------
__global__ __launch_bounds__(64)
void rope_split_kernel(const float* __restrict__ qkv,
                       const float* __restrict__ fc,
                       const float* __restrict__ fs,
                       float* __restrict__ Kg, float* __restrict__ Vg) {
    int t = blockIdx.x;
    int bk = blockIdx.y;
    int b = bk / NKVH, kv = bk % NKVH;
    int i = threadIdx.x;

    float c = fc[t * 64 + i];
    float s = fs[t * 64 + i];
    const float* row = qkv + ((size_t)(b * TT + t)) * N1;

    float k0 = row[EE + kv * DD + 2 * i];
    float k1 = row[EE + kv * DD + 2 * i + 1];
    float v0 = row[EE + KVD + kv * DD + 2 * i];
    float v1 = row[EE + KVD + kv * DD + 2 * i + 1];

    size_t o = ((size_t)(b * NKVH + kv) * TT + t) * DD + 2 * i;
    Kg[o]     = __uint_as_float(f2tf32(k0 * c - k1 * s));
    Kg[o + 1] = __uint_as_float(f2tf32(k0 * s + k1 * c));
    Vg[o]     = __uint_as_float(f2tf32(v0 * c - v1 * s));
    Vg[o + 1] = __uint_as_float(f2tf32(v0 * s + v1 * c));
}

// ---------------------------------------------------------------------------
// TF32 tensor-core flash attention (R4 version, verified; verbatim).
// ---------------------------------------------------------------------------
#define QS_S 132
#define KS_S 132
#define VS_S2 136
#define PS_S 68
#define SM_Q  0
#define SM_K  (128 * QS_S)
#define SM_V  (SM_K + 64 * KS_S)
#define SM_P  (SM_V + 64 * VS_S2)
#define SM_TOT (SM_P + 128 * PS_S)

__global__ __launch_bounds__(256, 1)
void attn_tf32(const float* __restrict__ qkv,
               const float* __restrict__ Kg,
               const float* __restrict__ Vg,
               float* __restrict__ Y) {
    extern __shared__ __align__(16) uint32_t smu[];
    uint32_t* Qs = smu + SM_Q;
    uint32_t* Ks = smu + SM_K;
    uint32_t* Vs = smu + SM_V;
    uint32_t* Ps = smu + SM_P;

    const int tid = threadIdx.x;
    const int lane = tid & 31;
    const int warp = tid >> 5;
    const int g4 = lane >> 2;
    const int a4 = lane & 3;

    const int qtile = (gridDim.x - 1) - blockIdx.x;
    const int bh = blockIdx.y;
    const int b = bh >> 4, h = bh & 15;
    const int kv = h >> 2;

    const float* qbase = qkv + ((size_t)(b * TT + qtile * 128)) * N1 + h * DD;
#pragma unroll
    for (int i = 0; i < 16; i++) {
        int idx = tid + i * 256;
        int row = idx >> 5;
        int col = (idx & 31) * 4;
        float4 q = *(const float4*)(qbase + (size_t)row * N1 + col);
        uint4 t;
        t.x = f2tf32(q.x); t.y = f2tf32(q.y);
        t.z = f2tf32(q.z); t.w = f2tf32(q.w);
        *(uint4*)(Qs + row * QS_S + col) = t;
    }

    float oacc[16][4];
#pragma unroll
    for (int nt = 0; nt < 16; nt++)
#pragma unroll
        for (int r = 0; r < 4; r++) oacc[nt][r] = 0.f;
    float m0 = -1e30f, m1 = -1e30f, l0 = 0.f, l1 = 0.f;

    const float scale = 0.08838834764831845f;
    const float* kbase = Kg + ((size_t)(b * NKVH + kv) * TT) * DD;
    const float* vbase = Vg + ((size_t)(b * NKVH + kv) * TT) * DD;

    const int rloc = warp * 16 + g4;
    const int grow0 = qtile * 128 + rloc;
    const int grow1 = grow0 + 8;

    const int njt = 2 * qtile + 2;
    for (int jt = 0; jt < njt; jt++) {
        __syncthreads();
#pragma unroll
        for (int i = 0; i < 8; i++) {
            int idx = tid + i * 256;
            int tok = idx >> 5;
            int col = (idx & 31) * 4;
            const float4* kp = (const float4*)(kbase + (size_t)(jt * 64 + tok) * DD + col);
            const float4* vp = (const float4*)(vbase + (size_t)(jt * 64 + tok) * DD + col);
            *(uint4*)(Ks + tok * KS_S + col) = *(const uint4*)kp;
            *(uint4*)(Vs + tok * VS_S2 + col) = *(const uint4*)vp;
        }
        __syncthreads();

        float sacc[8][4];
#pragma unroll
        for (int nt = 0; nt < 8; nt++)
#pragma unroll
            for (int r = 0; r < 4; r++) sacc[nt][r] = 0.f;

#pragma unroll
        for (int kt = 0; kt < 16; kt++) {
            uint32_t af[4];
            int c = kt * 8 + a4;
            af[0] = Qs[rloc * QS_S + c];
            af[1] = Qs[(rloc + 8) * QS_S + c];
            af[2] = Qs[rloc * QS_S + c + 4];
            af[3] = Qs[(rloc + 8) * QS_S + c + 4];
#pragma unroll
            for (int nt = 0; nt < 8; nt++) {
                int n = nt * 8 + g4;
                mma_tf32(sacc[nt], af, Ks[n * KS_S + kt * 8 + a4],
                         Ks[n * KS_S + kt * 8 + a4 + 4]);
            }
        }

        if (jt >= 2 * qtile) {
#pragma unroll
            for (int nt = 0; nt < 8; nt++) {
                int gc = jt * 64 + nt * 8 + 2 * a4;
                sacc[nt][0] = (gc     > grow0) ? -1e30f : sacc[nt][0] * scale;
                sacc[nt][1] = (gc + 1 > grow0) ? -1e30f : sacc[nt][1] * scale;
                sacc[nt][2] = (gc     > grow1) ? -1e30f : sacc[nt][2] * scale;
                sacc[nt][3] = (gc + 1 > grow1) ? -1e30f : sacc[nt][3] * scale;
            }
        } else {
#pragma unroll
            for (int nt = 0; nt < 8; nt++)
#pragma unroll
                for (int r = 0; r < 4; r++) sacc[nt][r] *= scale;
        }

        float rm0 = -1e30f, rm1 = -1e30f;
#pragma unroll
        for (int nt = 0; nt < 8; nt++) {
            rm0 = fmaxf(rm0, fmaxf(sacc[nt][0], sacc[nt][1]));
            rm1 = fmaxf(rm1, fmaxf(sacc[nt][2], sacc[nt][3]));
        }
        rm0 = fmaxf(rm0, __shfl_xor_sync(0xffffffffu, rm0, 1));
        rm0 = fmaxf(rm0, __shfl_xor_sync(0xffffffffu, rm0, 2));
        rm1 = fmaxf(rm1, __shfl_xor_sync(0xffffffffu, rm1, 1));
        rm1 = fmaxf(rm1, __shfl_xor_sync(0xffffffffu, rm1, 2));

        float mn0 = fmaxf(m0, rm0), mn1 = fmaxf(m1, rm1);
        float corr0 = __expf(m0 - mn0), corr1 = __expf(m1 - mn1);
        m0 = mn0; m1 = mn1;

        float rs0 = 0.f, rs1 = 0.f;
#pragma unroll
        for (int nt = 0; nt < 8; nt++) {
            float p0 = __expf(sacc[nt][0] - mn0);
            float p1 = __expf(sacc[nt][1] - mn0);
            float p2 = __expf(sacc[nt][2] - mn1);
            float p3 = __expf(sacc[nt][3] - mn1);
            rs0 += p0 + p1; rs1 += p2 + p3;
            int cc = nt * 8 + 2 * a4;
            *(uint2*)(Ps + rloc * PS_S + cc) = make_uint2(f2tf32(p0), f2tf32(p1));
            *(uint2*)(Ps + (rloc + 8) * PS_S + cc) = make_uint2(f2tf32(p2), f2tf32(p3));
        }
        rs0 += __shfl_xor_sync(0xffffffffu, rs0, 1);
        rs0 += __shfl_xor_sync(0xffffffffu, rs0, 2);
        rs1 += __shfl_xor_sync(0xffffffffu, rs1, 1);
        rs1 += __shfl_xor_sync(0xffffffffu, rs1, 2);
        l0 = l0 * corr0 + rs0;
        l1 = l1 * corr1 + rs1;

#pragma unroll
        for (int nt = 0; nt < 16; nt++) {
            oacc[nt][0] *= corr0; oacc[nt][1] *= corr0;
            oacc[nt][2] *= corr1; oacc[nt][3] *= corr1;
        }
        __syncwarp();

#pragma unroll
        for (int kt = 0; kt < 8; kt++) {
            uint32_t af[4];
            int c = kt * 8 + a4;
            af[0] = Ps[rloc * PS_S + c];
            af[1] = Ps[(rloc + 8) * PS_S + c];
            af[2] = Ps[rloc * PS_S + c + 4];
            af[3] = Ps[(rloc + 8) * PS_S + c + 4];
#pragma unroll
            for (int nt = 0; nt < 16; nt++) {
                mma_tf32(oacc[nt], af,
                         Vs[(kt * 8 + a4) * VS_S2 + nt * 8 + g4],
                         Vs[(kt * 8 + a4 + 4) * VS_S2 + nt * 8 + g4]);
            }
        }
    }

    float inv0 = 1.f / l0, inv1 = 1.f / l1;
    int t0 = qtile * 128 + rloc;
    float* y0 = Y + ((size_t)(b * TT + t0)) * EE + h * DD;
    float* y1 = Y + ((size_t)(b * TT + t0 + 8)) * EE + h * DD;
#pragma unroll
    for (int nt = 0; nt < 16; nt++) {
        int cc = nt * 8 + 2 * a4;
        *(float2*)(y0 + cc) = make_float2(
            __uint_as_float(f2tf32(oacc[nt][0] * inv0)),
            __uint_as_float(f2tf32(oacc[nt][1] * inv0)));
        *(float2*)(y1 + cc) = make_float2(
            __uint_as_float(f2tf32(oacc[nt][2] * inv1)),
            __uint_as_float(f2tf32(oacc[nt][3] * inv1)));
    }
}

// ---------------------------------------------------------------------------
extern "C" void kernel_launch(void* const* d_in, const int* in_sizes, int n_in,
                              void* d_out, int out_size) {
    const float* x  = (const float*)d_in[0];
    const float* Wa = (const float*)d_in[1];
    const float* ba = (const float*)d_in[2];
    const float* Wp = (const float*)d_in[3];
    const float* fc = (const float*)d_in[4];
    const float* fs = (const float*)d_in[5];
    float* out = (float*)d_out;

    float *qkv, *kg, *vg, *yb, *xt, *wat, *wpt;
    cudaGetSymbolAddress((void**)&qkv, g_qkv);
    cudaGetSymbolAddress((void**)&kg, g_k);
    cudaGetSymbolAddress((void**)&vg, g_v);
    cudaGetSymbolAddress((void**)&yb, g_y);
    cudaGetSymbolAddress((void**)&xt, g_xt);
    cudaGetSymbolAddress((void**)&wat, g_wat);
    cudaGetSymbolAddress((void**)&wpt, g_wpt);

    // operand prep
    conv_tf32<<<(MM * EE / 4 + 255) / 256, 256>>>(x, xt, MM * EE / 4);
    transpose_tf32<<<dim3(N1 / 32, EE / 32), dim3(32, 8)>>>(Wa, wat, EE, N1);
    transpose_tf32<<<dim3(EE / 32, EE / 32), dim3(32, 8)>>>(Wp, wpt, EE, EE);

    int gsm = STAGES * STG_BYTES * 2;
    cudaFuncSetAttribute(gemm_v2, cudaFuncAttributeMaxDynamicSharedMemorySize, gsm);

    // 1) QKV GEMM (+bias)
    gemm_v2<<<dim3(N1 / 128, MM / 128), 256, gsm>>>(xt, wat, ba, qkv, MM, N1, EE);

    // 2) RoPE on K and V
    rope_split_kernel<<<dim3(TT, BB * NKVH), 64>>>(qkv, fc, fs, kg, vg);

    // 3) attention
    int smem_bytes = SM_TOT * (int)sizeof(uint32_t);
    cudaFuncSetAttribute(attn_tf32, cudaFuncAttributeMaxDynamicSharedMemorySize,
                         smem_bytes);
    attn_tf32<<<dim3(TT / 128, BB * HH), 256, smem_bytes>>>(qkv, kg, vg, yb);

    // 4) output projection
    gemm_v2<<<dim3(EE / 128, MM / 128), 256, gsm>>>(yb, wpt, nullptr, out, MM, EE, EE);
}

// round 11
// speedup vs baseline: 1.2265x; 1.0965x over previous
#include <cuda_runtime.h>
#include <cuda_bf16.h>
#include <math.h>
#include <stdint.h>

// Problem constants (QwenGroupedQueryAttention_44100724195922)
#define BB   2
#define TT   2048
#define EE   2048
#define HH   16
#define DD   128
#define GG   4
#define NKVH 4
#define KVD  512
#define N1   3072
#define MM   4096

__device__ float g_qkv[(size_t)MM * N1];             // fp32
__device__ float g_k[(size_t)BB * NKVH * TT * DD];   // tf32 bits
__device__ float g_v[(size_t)BB * NKVH * TT * DD];   // tf32 bits
__device__ float g_y[(size_t)MM * EE];               // tf32 bits (attn out)
__device__ float g_xt[(size_t)MM * EE];              // x as tf32 bits
__device__ float g_wat[(size_t)N1 * EE];             // Wa^T [N1][E] tf32 bits
__device__ float g_wpt[(size_t)EE * EE];             // Wp^T [E][E] tf32 bits

__device__ __forceinline__ uint32_t f2tf32(float x) {
    uint32_t r;
    asm("cvt.rna.tf32.f32 %0, %1;" : "=r"(r) : "f"(x));
    return r;
}

__device__ __forceinline__ void mma_tf32(float c[4], const uint32_t a[4],
                                         uint32_t b0, uint32_t b1) {
    asm volatile(
        "mma.sync.aligned.m16n8k8.row.col.f32.tf32.tf32.f32 "
        "{%0,%1,%2,%3}, {%4,%5,%6,%7}, {%8,%9}, {%0,%1,%2,%3};"
        : "+f"(c[0]), "+f"(c[1]), "+f"(c[2]), "+f"(c[3])
        : "r"(a[0]), "r"(a[1]), "r"(a[2]), "r"(a[3]), "r"(b0), "r"(b1));
}

__device__ __forceinline__ void cp16(uint32_t dst, const void* src) {
    asm volatile("cp.async.cg.shared.global [%0], [%1], 16;"
                 :: "r"(dst), "l"(src));
}
__device__ __forceinline__ void ldsm_x4(uint32_t* r, uint32_t a) {
    asm volatile("ldmatrix.sync.aligned.m8n8.x4.shared.b16 {%0,%1,%2,%3}, [%4];"
                 : "=r"(r[0]), "=r"(r[1]), "=r"(r[2]), "=r"(r[3]) : "r"(a));
}
__device__ __forceinline__ void ldsm_x2(uint32_t* r, uint32_t a) {
    asm volatile("ldmatrix.sync.aligned.m8n8.x2.shared.b16 {%0,%1}, [%2];"
                 : "=r"(r[0]), "=r"(r[1]) : "r"(a));
}

// ---------------------------------------------------------------------------
// Elementwise fp32 -> tf32 bits
// ---------------------------------------------------------------------------
__global__ __launch_bounds__(256)
void conv_tf32(const float* __restrict__ in, float* __restrict__ out, int n4) {
    int i = blockIdx.x * 256 + threadIdx.x;
    if (i >= n4) return;
    float4 v = ((const float4*)in)[i];
    uint4 t;
    t.x = f2tf32(v.x); t.y = f2tf32(v.y); t.z = f2tf32(v.z); t.w = f2tf32(v.w);
    ((uint4*)out)[i] = t;
}

// ---------------------------------------------------------------------------
// Transpose + tf32: W[K][N] -> Wt[N][K]
// ---------------------------------------------------------------------------
__global__ __launch_bounds__(256)
void transpose_tf32(const float* __restrict__ W, float* __restrict__ Wt,
                    int K, int N) {
    __shared__ float tile[32][33];
    int n0 = blockIdx.x * 32, k0 = blockIdx.y * 32;
    int tx = threadIdx.x, ty = threadIdx.y;  // (32, 8)
#pragma unroll
    for (int j = 0; j < 4; j++)
        tile[ty + j * 8][tx] = W[(size_t)(k0 + ty + j * 8) * N + n0 + tx];
    __syncthreads();
#pragma unroll
    for (int j = 0; j < 4; j++)
        Wt[(size_t)(n0 + ty + j * 8) * K + k0 + tx] =
            __uint_as_float(f2tf32(tile[tx][ty + j * 8]));
}

// ---------------------------------------------------------------------------
// TF32 GEMM v4: C[M,N] = A[M,K] @ Bt[N,K]^T (+bias)
// 64x128 tile, 128 threads (warps 2x2, warp tile 32x64), BK=32,
// 2-stage cp.async double buffer, 48KB smem -> 4 CTAs/SM (32 warps/SM).
// Fragment algebra identical to verified gemm_v2 (A x4, B x2).
// ---------------------------------------------------------------------------
#define V4_A_BYTES 8192            // 64 * 32 * 4
#define V4_B_BYTES 16384           // 128 * 32 * 4
#define V4_STG (V4_A_BYTES + V4_B_BYTES)
#define V4_SMEM (2 * V4_STG)       // 49152

__global__ __launch_bounds__(128, 4)
void gemm_v4(const float* __restrict__ A, const float* __restrict__ Bt,
             const float* __restrict__ bias, float* __restrict__ C,
             int M, int N, int K) {
    extern __shared__ __align__(16) char smraw[];
    const uint32_t sbase = (uint32_t)__cvta_generic_to_shared(smraw);

    const int tid = threadIdx.x;
    const int lane = tid & 31;
    const int wid = tid >> 5;
    const int wm = wid >> 1;   // 0..1 -> m offset 32*wm
    const int wn = wid & 1;    // 0..1 -> n offset 64*wn
    const int bm = blockIdx.y * 64, bn = blockIdx.x * 128;

    float acc[2][8][4];
#pragma unroll
    for (int mi = 0; mi < 2; mi++)
#pragma unroll
        for (int ni = 0; ni < 8; ni++)
#pragma unroll
            for (int r = 0; r < 4; r++) acc[mi][ni][r] = 0.f;

    const int srow = tid >> 3;   // 0..15
    const int sk4 = tid & 7;     // 0..7

    auto stage_fn = [&](int kt, int stg) {
        uint32_t sa = sbase + stg * V4_STG;
        uint32_t sb = sa + V4_A_BYTES;
        const float* ap = A + (size_t)bm * K + kt * 32 + sk4 * 4;
        const float* bp = Bt + (size_t)bn * K + kt * 32 + sk4 * 4;
#pragma unroll
        for (int i = 0; i < 4; i++) {
            int row = srow + i * 16;
            cp16(sa + ((row * 8 + (sk4 ^ (row & 7))) << 4), ap + (size_t)row * K);
        }
#pragma unroll
        for (int i = 0; i < 8; i++) {
            int row = srow + i * 16;
            cp16(sb + ((row * 8 + (sk4 ^ (row & 7))) << 4), bp + (size_t)row * K);
        }
        asm volatile("cp.async.commit_group;");
    };

    const int nkt = K / 32;
    stage_fn(0, 0);

    const int mLane = wm * 32 + (lane & 15);   // + mi*16
    const int k4A_base = (lane >> 4);          // + s*2
    const int nLane = wn * 64 + (lane & 7);    // + ni*8
    const int k4B_base = ((lane >> 3) & 1);    // + s*2

    for (int kt = 0; kt < nkt; kt++) {
        int cur = kt & 1;
        asm volatile("cp.async.wait_group 0;");
        __syncthreads();
        if (kt + 1 < nkt) stage_fn(kt + 1, cur ^ 1);

        uint32_t aBase = sbase + cur * V4_STG;
        uint32_t bBase = aBase + V4_A_BYTES;
#pragma unroll
        for (int s = 0; s < 4; s++) {
            uint32_t af[2][4];
            int k4a = s * 2 + k4A_base;
#pragma unroll
            for (int mi = 0; mi < 2; mi++) {
                int m = mLane + mi * 16;
                ldsm_x4(af[mi], aBase + ((m * 8 + (k4a ^ (m & 7))) << 4));
            }
            uint32_t bf[8][2];
            int k4b = s * 2 + k4B_base;
#pragma unroll
            for (int ni = 0; ni < 8; ni++) {
                int n = nLane + ni * 8;
                ldsm_x2(bf[ni], bBase + ((n * 8 + (k4b ^ (n & 7))) << 4));
            }
#pragma unroll
            for (int mi = 0; mi < 2; mi++)
#pragma unroll
                for (int ni = 0; ni < 8; ni++)
                    mma_tf32(acc[mi][ni], af[mi], bf[ni][0], bf[ni][1]);
        }
        // no trailing barrier: stage(kt+1) wrote buffer cur^1 (not cur);
        // buffer cur is protected by the next iteration's leading barrier.
    }

    const int g4 = lane >> 2, a4 = lane & 3;
#pragma unroll
    for (int mi = 0; mi < 2; mi++) {
        int row = bm + wm * 32 + mi * 16 + g4;
#pragma unroll
        for (int ni = 0; ni < 8; ni++) {
            int col = bn + wn * 64 + ni * 8 + 2 * a4;
            float bx = 0.f, by = 0.f;
            if (bias) { bx = bias[col]; by = bias[col + 1]; }
            *(float2*)(C + (size_t)row * N + col) =
                make_float2(acc[mi][ni][0] + bx, acc[mi][ni][1] + by);
            *(float2*)(C + (size_t)(row + 8) * N + col) =
                make_float2(acc[mi][ni][2] + bx, acc[mi][ni][3] + by);
        }
    }
}

// ---------------------------------------------------------------------------
// RoPE on K and V (per reference), split into [B,NKV,T,D], TF32 bits.
// ---------------------------------------------------------------------------
__global__ __launch_bounds__(64)
void rope_split_kernel(const float* __restrict__ qkv,
                       const float* __restrict__ fc,
                       const float* __restrict__ fs,
                       float* __restrict__ Kg, float* __restrict__ Vg) {
    int t = blockIdx.x;
    int bk = blockIdx.y;
    int b = bk / NKVH, kv = bk % NKVH;
    int i = threadIdx.x;

    float c = fc[t * 64 + i];
    float s = fs[t * 64 + i];
    const float* row = qkv + ((size_t)(b * TT + t)) * N1;

    float k0 = row[EE + kv * DD + 2 * i];
    float k1 = row[EE + kv * DD + 2 * i + 1];
    float v0 = row[EE + KVD + kv * DD + 2 * i];
    float v1 = row[EE + KVD + kv * DD + 2 * i + 1];

    size_t o = ((size_t)(b * NKVH + kv) * TT + t) * DD + 2 * i;
    Kg[o]     = __uint_as_float(f2tf32(k0 * c - k1 * s));
    Kg[o + 1] = __uint_as_float(f2tf32(k0 * s + k1 * c));
    Vg[o]     = __uint_as_float(f2tf32(v0 * c - v1 * s));
    Vg[o + 1] = __uint_as_float(f2tf32(v0 * s + v1 * c));
}

// ---------------------------------------------------------------------------
// TF32 tensor-core flash attention (R4 version, verified; verbatim).
// ---------------------------------------------------------------------------
#define QS_S 132
#define KS_S 132
#define VS_S2 136
#define PS_S 68
#define SM_Q  0
#define SM_K  (128 * QS_S)
#define SM_V  (SM_K + 64 * KS_S)
#define SM_P  (SM_V + 64 * VS_S2)
#define SM_TOT (SM_P + 128 * PS_S)

__global__ __launch_bounds__(256, 1)
void attn_tf32(const float* __restrict__ qkv,
               const float* __restrict__ Kg,
               const float* __restrict__ Vg,
               float* __restrict__ Y) {
    extern __shared__ __align__(16) uint32_t smu[];
    uint32_t* Qs = smu + SM_Q;
    uint32_t* Ks = smu + SM_K;
    uint32_t* Vs = smu + SM_V;
    uint32_t* Ps = smu + SM_P;

    const int tid = threadIdx.x;
    const int lane = tid & 31;
    const int warp = tid >> 5;
    const int g4 = lane >> 2;
    const int a4 = lane & 3;

    const int qtile = (gridDim.x - 1) - blockIdx.x;
    const int bh = blockIdx.y;
    const int b = bh >> 4, h = bh & 15;
    const int kv = h >> 2;

    const float* qbase = qkv + ((size_t)(b * TT + qtile * 128)) * N1 + h * DD;
#pragma unroll
    for (int i = 0; i < 16; i++) {
        int idx = tid + i * 256;
        int row = idx >> 5;
        int col = (idx & 31) * 4;
        float4 q = *(const float4*)(qbase + (size_t)row * N1 + col);
        uint4 t;
        t.x = f2tf32(q.x); t.y = f2tf32(q.y);
        t.z = f2tf32(q.z); t.w = f2tf32(q.w);
        *(uint4*)(Qs + row * QS_S + col) = t;
    }

    float oacc[16][4];
#pragma unroll
    for (int nt = 0; nt < 16; nt++)
#pragma unroll
        for (int r = 0; r < 4; r++) oacc[nt][r] = 0.f;
    float m0 = -1e30f, m1 = -1e30f, l0 = 0.f, l1 = 0.f;

    const float scale = 0.08838834764831845f;
    const float* kbase = Kg + ((size_t)(b * NKVH + kv) * TT) * DD;
    const float* vbase = Vg + ((size_t)(b * NKVH + kv) * TT) * DD;

    const int rloc = warp * 16 + g4;
    const int grow0 = qtile * 128 + rloc;
    const int grow1 = grow0 + 8;

    const int njt = 2 * qtile + 2;
    for (int jt = 0; jt < njt; jt++) {
        __syncthreads();
#pragma unroll
        for (int i = 0; i < 8; i++) {
            int idx = tid + i * 256;
            int tok = idx >> 5;
            int col = (idx & 31) * 4;
            const float4* kp = (const float4*)(kbase + (size_t)(jt * 64 + tok) * DD + col);
            const float4* vp = (const float4*)(vbase + (size_t)(jt * 64 + tok) * DD + col);
            *(uint4*)(Ks + tok * KS_S + col) = *(const uint4*)kp;
            *(uint4*)(Vs + tok * VS_S2 + col) = *(const uint4*)vp;
        }
        __syncthreads();

        float sacc[8][4];
#pragma unroll
        for (int nt = 0; nt < 8; nt++)
#pragma unroll
            for (int r = 0; r < 4; r++) sacc[nt][r] = 0.f;

#pragma unroll
        for (int kt = 0; kt < 16; kt++) {
            uint32_t af[4];
            int c = kt * 8 + a4;
            af[0] = Qs[rloc * QS_S + c];
            af[1] = Qs[(rloc + 8) * QS_S + c];
            af[2] = Qs[rloc * QS_S + c + 4];
            af[3] = Qs[(rloc + 8) * QS_S + c + 4];
#pragma unroll
            for (int nt = 0; nt < 8; nt++) {
                int n = nt * 8 + g4;
                mma_tf32(sacc[nt], af, Ks[n * KS_S + kt * 8 + a4],
                         Ks[n * KS_S + kt * 8 + a4 + 4]);
            }
        }

        if (jt >= 2 * qtile) {
#pragma unroll
            for (int nt = 0; nt < 8; nt++) {
                int gc = jt * 64 + nt * 8 + 2 * a4;
                sacc[nt][0] = (gc     > grow0) ? -1e30f : sacc[nt][0] * scale;
                sacc[nt][1] = (gc + 1 > grow0) ? -1e30f : sacc[nt][1] * scale;
                sacc[nt][2] = (gc     > grow1) ? -1e30f : sacc[nt][2] * scale;
                sacc[nt][3] = (gc + 1 > grow1) ? -1e30f : sacc[nt][3] * scale;
            }
        } else {
#pragma unroll
            for (int nt = 0; nt < 8; nt++)
#pragma unroll
                for (int r = 0; r < 4; r++) sacc[nt][r] *= scale;
        }

        float rm0 = -1e30f, rm1 = -1e30f;
#pragma unroll
        for (int nt = 0; nt < 8; nt++) {
            rm0 = fmaxf(rm0, fmaxf(sacc[nt][0], sacc[nt][1]));
            rm1 = fmaxf(rm1, fmaxf(sacc[nt][2], sacc[nt][3]));
        }
        rm0 = fmaxf(rm0, __shfl_xor_sync(0xffffffffu, rm0, 1));
        rm0 = fmaxf(rm0, __shfl_xor_sync(0xffffffffu, rm0, 2));
        rm1 = fmaxf(rm1, __shfl_xor_sync(0xffffffffu, rm1, 1));
        rm1 = fmaxf(rm1, __shfl_xor_sync(0xffffffffu, rm1, 2));

        float mn0 = fmaxf(m0, rm0), mn1 = fmaxf(m1, rm1);
        float corr0 = __expf(m0 - mn0), corr1 = __expf(m1 - mn1);
        m0 = mn0; m1 = mn1;

        float rs0 = 0.f, rs1 = 0.f;
#pragma unroll
        for (int nt = 0; nt < 8; nt++) {
            float p0 = __expf(sacc[nt][0] - mn0);
            float p1 = __expf(sacc[nt][1] - mn0);
            float p2 = __expf(sacc[nt][2] - mn1);
            float p3 = __expf(sacc[nt][3] - mn1);
            rs0 += p0 + p1; rs1 += p2 + p3;
            int cc = nt * 8 + 2 * a4;
            *(uint2*)(Ps + rloc * PS_S + cc) = make_uint2(f2tf32(p0), f2tf32(p1));
            *(uint2*)(Ps + (rloc + 8) * PS_S + cc) = make_uint2(f2tf32(p2), f2tf32(p3));
        }
        rs0 += __shfl_xor_sync(0xffffffffu, rs0, 1);
        rs0 += __shfl_xor_sync(0xffffffffu, rs0, 2);
        rs1 += __shfl_xor_sync(0xffffffffu, rs1, 1);
        rs1 += __shfl_xor_sync(0xffffffffu, rs1, 2);
        l0 = l0 * corr0 + rs0;
        l1 = l1 * corr1 + rs1;

#pragma unroll
        for (int nt = 0; nt < 16; nt++) {
            oacc[nt][0] *= corr0; oacc[nt][1] *= corr0;
            oacc[nt][2] *= corr1; oacc[nt][3] *= corr1;
        }
        __syncwarp();

#pragma unroll
        for (int kt = 0; kt < 8; kt++) {
            uint32_t af[4];
            int c = kt * 8 + a4;
            af[0] = Ps[rloc * PS_S + c];
            af[1] = Ps[(rloc + 8) * PS_S + c];
            af[2] = Ps[rloc * PS_S + c + 4];
            af[3] = Ps[(rloc + 8) * PS_S + c + 4];
#pragma unroll
            for (int nt = 0; nt < 16; nt++) {
                mma_tf32(oacc[nt], af,
                         Vs[(kt * 8 + a4) * VS_S2 + nt * 8 + g4],
                         Vs[(kt * 8 + a4 + 4) * VS_S2 + nt * 8 + g4]);
            }
        }
    }

    float inv0 = 1.f / l0, inv1 = 1.f / l1;
    int t0 = qtile * 128 + rloc;
    float* y0 = Y + ((size_t)(b * TT + t0)) * EE + h * DD;
    float* y1 = Y + ((size_t)(b * TT + t0 + 8)) * EE + h * DD;
#pragma unroll
    for (int nt = 0; nt < 16; nt++) {
        int cc = nt * 8 + 2 * a4;
        *(float2*)(y0 + cc) = make_float2(
            __uint_as_float(f2tf32(oacc[nt][0] * inv0)),
            __uint_as_float(f2tf32(oacc[nt][1] * inv0)));
        *(float2*)(y1 + cc) = make_float2(
            __uint_as_float(f2tf32(oacc[nt][2] * inv1)),
            __uint_as_float(f2tf32(oacc[nt][3] * inv1)));
    }
}

// ---------------------------------------------------------------------------
extern "C" void kernel_launch(void* const* d_in, const int* in_sizes, int n_in,
                              void* d_out, int out_size) {
    const float* x  = (const float*)d_in[0];
    const float* Wa = (const float*)d_in[1];
    const float* ba = (const float*)d_in[2];
    const float* Wp = (const float*)d_in[3];
    const float* fc = (const float*)d_in[4];
    const float* fs = (const float*)d_in[5];
    float* out = (float*)d_out;

    float *qkv, *kg, *vg, *yb, *xt, *wat, *wpt;
    cudaGetSymbolAddress((void**)&qkv, g_qkv);
    cudaGetSymbolAddress((void**)&kg, g_k);
    cudaGetSymbolAddress((void**)&vg, g_v);
    cudaGetSymbolAddress((void**)&yb, g_y);
    cudaGetSymbolAddress((void**)&xt, g_xt);
    cudaGetSymbolAddress((void**)&wat, g_wat);
    cudaGetSymbolAddress((void**)&wpt, g_wpt);

    // operand prep
    conv_tf32<<<(MM * EE / 4 + 255) / 256, 256>>>(x, xt, MM * EE / 4);
    transpose_tf32<<<dim3(N1 / 32, EE / 32), dim3(32, 8)>>>(Wa, wat, EE, N1);
    transpose_tf32<<<dim3(EE / 32, EE / 32), dim3(32, 8)>>>(Wp, wpt, EE, EE);

    cudaFuncSetAttribute(gemm_v4, cudaFuncAttributeMaxDynamicSharedMemorySize,
                         V4_SMEM);

    // 1) QKV GEMM (+bias)
    gemm_v4<<<dim3(N1 / 128, MM / 64), 128, V4_SMEM>>>(xt, wat, ba, qkv,
                                                       MM, N1, EE);

    // 2) RoPE on K and V
    rope_split_kernel<<<dim3(TT, BB * NKVH), 64>>>(qkv, fc, fs, kg, vg);

    // 3) attention
    int smem_bytes = SM_TOT * (int)sizeof(uint32_t);
    cudaFuncSetAttribute(attn_tf32, cudaFuncAttributeMaxDynamicSharedMemorySize,
                         smem_bytes);
    attn_tf32<<<dim3(TT / 128, BB * HH), 256, smem_bytes>>>(qkv, kg, vg, yb);

    // 4) output projection
    gemm_v4<<<dim3(EE / 128, MM / 64), 128, V4_SMEM>>>(yb, wpt, nullptr, out,
                                                       MM, EE, EE);
}

// round 12
// speedup vs baseline: 1.2290x; 1.0020x over previous
#include <cuda_runtime.h>
#include <cuda_bf16.h>
#include <math.h>
#include <stdint.h>

// Problem constants (QwenGroupedQueryAttention_44100724195922)
#define BB   2
#define TT   2048
#define EE   2048
#define HH   16
#define DD   128
#define GG   4
#define NKVH 4
#define KVD  512
#define N1   3072
#define MM   4096

__device__ float g_qkv[(size_t)MM * N1];             // fp32 (Q region used)
__device__ float g_k[(size_t)BB * NKVH * TT * DD];   // tf32 bits
__device__ float g_v[(size_t)BB * NKVH * TT * DD];   // tf32 bits
__device__ float g_y[(size_t)MM * EE];               // tf32 bits (attn out)
__device__ float g_xt[(size_t)MM * EE];              // x as tf32 bits
__device__ float g_wat[(size_t)N1 * EE];             // Wa^T [N1][E] tf32 bits
__device__ float g_wpt[(size_t)EE * EE];             // Wp^T [E][E] tf32 bits

__device__ __forceinline__ uint32_t f2tf32(float x) {
    uint32_t r;
    asm("cvt.rna.tf32.f32 %0, %1;" : "=r"(r) : "f"(x));
    return r;
}

__device__ __forceinline__ void mma_tf32(float c[4], const uint32_t a[4],
                                         uint32_t b0, uint32_t b1) {
    asm volatile(
        "mma.sync.aligned.m16n8k8.row.col.f32.tf32.tf32.f32 "
        "{%0,%1,%2,%3}, {%4,%5,%6,%7}, {%8,%9}, {%0,%1,%2,%3};"
        : "+f"(c[0]), "+f"(c[1]), "+f"(c[2]), "+f"(c[3])
        : "r"(a[0]), "r"(a[1]), "r"(a[2]), "r"(a[3]), "r"(b0), "r"(b1));
}

__device__ __forceinline__ void cp16(uint32_t dst, const void* src) {
    asm volatile("cp.async.cg.shared.global [%0], [%1], 16;"
                 :: "r"(dst), "l"(src));
}
__device__ __forceinline__ void ldsm_x4(uint32_t* r, uint32_t a) {
    asm volatile("ldmatrix.sync.aligned.m8n8.x4.shared.b16 {%0,%1,%2,%3}, [%4];"
                 : "=r"(r[0]), "=r"(r[1]), "=r"(r[2]), "=r"(r[3]) : "r"(a));
}
__device__ __forceinline__ void ldsm_x2(uint32_t* r, uint32_t a) {
    asm volatile("ldmatrix.sync.aligned.m8n8.x2.shared.b16 {%0,%1}, [%2];"
                 : "=r"(r[0]), "=r"(r[1]) : "r"(a));
}

// ---------------------------------------------------------------------------
// Elementwise fp32 -> tf32 bits
// ---------------------------------------------------------------------------
__global__ __launch_bounds__(256)
void conv_tf32(const float* __restrict__ in, float* __restrict__ out, int n4) {
    int i = blockIdx.x * 256 + threadIdx.x;
    if (i >= n4) return;
    float4 v = ((const float4*)in)[i];
    uint4 t;
    t.x = f2tf32(v.x); t.y = f2tf32(v.y); t.z = f2tf32(v.z); t.w = f2tf32(v.w);
    ((uint4*)out)[i] = t;
}

// ---------------------------------------------------------------------------
// Transpose + tf32: W[K][N] -> Wt[N][K]
// ---------------------------------------------------------------------------
__global__ __launch_bounds__(256)
void transpose_tf32(const float* __restrict__ W, float* __restrict__ Wt,
                    int K, int N) {
    __shared__ float tile[32][33];
    int n0 = blockIdx.x * 32, k0 = blockIdx.y * 32;
    int tx = threadIdx.x, ty = threadIdx.y;  // (32, 8)
#pragma unroll
    for (int j = 0; j < 4; j++)
        tile[ty + j * 8][tx] = W[(size_t)(k0 + ty + j * 8) * N + n0 + tx];
    __syncthreads();
#pragma unroll
    for (int j = 0; j < 4; j++)
        Wt[(size_t)(n0 + ty + j * 8) * K + k0 + tx] =
            __uint_as_float(f2tf32(tile[tx][ty + j * 8]));
}

// ---------------------------------------------------------------------------
// TF32 GEMM v4 + fused RoPE epilogue.
// 64x128 tile, 128 threads (warps 2x2, warp tile 32x64), BK=32,
// 2-stage cp.async double buffer, 48KB smem -> 4 CTAs/SM.
// When fuse_rope != 0 and the N-tile lies in the K/V column range, the
// epilogue applies bias + RoPE (fp32) and writes tf32 bits to Kg/Vg instead
// of C. Every 128-wide tile is entirely within one head (branch uniform).
// ---------------------------------------------------------------------------
#define V4_A_BYTES 8192            // 64 * 32 * 4
#define V4_B_BYTES 16384           // 128 * 32 * 4
#define V4_STG (V4_A_BYTES + V4_B_BYTES)
#define V4_SMEM (2 * V4_STG)       // 49152

__global__ __launch_bounds__(128, 4)
void gemm_v4(const float* __restrict__ A, const float* __restrict__ Bt,
             const float* __restrict__ bias, float* __restrict__ C,
             int M, int N, int K,
             int fuse_rope,
             const float* __restrict__ fc, const float* __restrict__ fs,
             float* __restrict__ Kg, float* __restrict__ Vg) {
    extern __shared__ __align__(16) char smraw[];
    const uint32_t sbase = (uint32_t)__cvta_generic_to_shared(smraw);

    const int tid = threadIdx.x;
    const int lane = tid & 31;
    const int wid = tid >> 5;
    const int wm = wid >> 1;   // 0..1 -> m offset 32*wm
    const int wn = wid & 1;    // 0..1 -> n offset 64*wn
    const int bm = blockIdx.y * 64, bn = blockIdx.x * 128;

    float acc[2][8][4];
#pragma unroll
    for (int mi = 0; mi < 2; mi++)
#pragma unroll
        for (int ni = 0; ni < 8; ni++)
#pragma unroll
            for (int r = 0; r < 4; r++) acc[mi][ni][r] = 0.f;

    const int srow = tid >> 3;   // 0..15
    const int sk4 = tid & 7;     // 0..7

    auto stage_fn = [&](int kt, int stg) {
        uint32_t sa = sbase + stg * V4_STG;
        uint32_t sb = sa + V4_A_BYTES;
        const float* ap = A + (size_t)bm * K + kt * 32 + sk4 * 4;
        const float* bp = Bt + (size_t)bn * K + kt * 32 + sk4 * 4;
#pragma unroll
        for (int i = 0; i < 4; i++) {
            int row = srow + i * 16;
            cp16(sa + ((row * 8 + (sk4 ^ (row & 7))) << 4), ap + (size_t)row * K);
        }
#pragma unroll
        for (int i = 0; i < 8; i++) {
            int row = srow + i * 16;
            cp16(sb + ((row * 8 + (sk4 ^ (row & 7))) << 4), bp + (size_t)row * K);
        }
        asm volatile("cp.async.commit_group;");
    };

    const int nkt = K / 32;
    stage_fn(0, 0);

    const int mLane = wm * 32 + (lane & 15);   // + mi*16
    const int k4A_base = (lane >> 4);          // + s*2
    const int nLane = wn * 64 + (lane & 7);    // + ni*8
    const int k4B_base = ((lane >> 3) & 1);    // + s*2

    for (int kt = 0; kt < nkt; kt++) {
        int cur = kt & 1;
        asm volatile("cp.async.wait_group 0;");
        __syncthreads();
        if (kt + 1 < nkt) stage_fn(kt + 1, cur ^ 1);

        uint32_t aBase = sbase + cur * V4_STG;
        uint32_t bBase = aBase + V4_A_BYTES;
#pragma unroll
        for (int s = 0; s < 4; s++) {
            uint32_t af[2][4];
            int k4a = s * 2 + k4A_base;
#pragma unroll
            for (int mi = 0; mi < 2; mi++) {
                int m = mLane + mi * 16;
                ldsm_x4(af[mi], aBase + ((m * 8 + (k4a ^ (m & 7))) << 4));
            }
            uint32_t bf[8][2];
            int k4b = s * 2 + k4B_base;
#pragma unroll
            for (int ni = 0; ni < 8; ni++) {
                int n = nLane + ni * 8;
                ldsm_x2(bf[ni], bBase + ((n * 8 + (k4b ^ (n & 7))) << 4));
            }
#pragma unroll
            for (int mi = 0; mi < 2; mi++)
#pragma unroll
                for (int ni = 0; ni < 8; ni++)
                    mma_tf32(acc[mi][ni], af[mi], bf[ni][0], bf[ni][1]);
        }
    }

    const int g4 = lane >> 2, a4 = lane & 3;

    // classify tile (uniform per block)
    bool isKV = false, isV = false;
    int kvh = 0;
    if (fuse_rope && bn >= EE) {
        isKV = true;
        if (bn < EE + KVD) kvh = (bn - EE) >> 7;
        else { isV = true; kvh = (bn - EE - KVD) >> 7; }
    }

    if (!isKV) {
#pragma unroll
        for (int mi = 0; mi < 2; mi++) {
            int row = bm + wm * 32 + mi * 16 + g4;
#pragma unroll
            for (int ni = 0; ni < 8; ni++) {
                int col = bn + wn * 64 + ni * 8 + 2 * a4;
                float bx = 0.f, by = 0.f;
                if (bias) { bx = bias[col]; by = bias[col + 1]; }
                *(float2*)(C + (size_t)row * N + col) =
                    make_float2(acc[mi][ni][0] + bx, acc[mi][ni][1] + by);
                *(float2*)(C + (size_t)(row + 8) * N + col) =
                    make_float2(acc[mi][ni][2] + bx, acc[mi][ni][3] + by);
            }
        }
    } else {
        float* dstBase = isV ? Vg : Kg;
#pragma unroll
        for (int mi = 0; mi < 2; mi++) {
            int row = bm + wm * 32 + mi * 16 + g4;
            int b = row >> 11;
            int t = row & 2047;
            float* dst = dstBase + ((size_t)(b * NKVH + kvh) * TT) * DD;
#pragma unroll
            for (int ni = 0; ni < 8; ni++) {
                int col = bn + wn * 64 + ni * 8 + 2 * a4;   // global col
                int d = wn * 64 + ni * 8 + 2 * a4;          // head-local [0,128)
                int i = d >> 1;
                float bx = 0.f, by = 0.f;
                if (bias) { bx = bias[col]; by = bias[col + 1]; }
                // row t
                {
                    float c0 = fc[t * 64 + i], s0 = fs[t * 64 + i];
                    float v0 = acc[mi][ni][0] + bx;
                    float v1 = acc[mi][ni][1] + by;
                    *(float2*)(dst + (size_t)t * DD + d) = make_float2(
                        __uint_as_float(f2tf32(v0 * c0 - v1 * s0)),
                        __uint_as_float(f2tf32(v0 * s0 + v1 * c0)));
                }
                // row t+8 (same b: 64-row block never straddles the 2048 line)
                {
                    float c1 = fc[(t + 8) * 64 + i], s1 = fs[(t + 8) * 64 + i];
                    float v0 = acc[mi][ni][2] + bx;
                    float v1 = acc[mi][ni][3] + by;
                    *(float2*)(dst + (size_t)(t + 8) * DD + d) = make_float2(
                        __uint_as_float(f2tf32(v0 * c1 - v1 * s1)),
                        __uint_as_float(f2tf32(v0 * s1 + v1 * c1)));
                }
            }
        }
    }
}

// ---------------------------------------------------------------------------
// TF32 tensor-core flash attention (R4 version, verified; verbatim).
// ---------------------------------------------------------------------------
#define QS_S 132
#define KS_S 132
#define VS_S2 136
#define PS_S 68
#define SM_Q  0
#define SM_K  (128 * QS_S)
#define SM_V  (SM_K + 64 * KS_S)
#define SM_P  (SM_V + 64 * VS_S2)
#define SM_TOT (SM_P + 128 * PS_S)

__global__ __launch_bounds__(256, 1)
void attn_tf32(const float* __restrict__ qkv,
               const float* __restrict__ Kg,
               const float* __restrict__ Vg,
               float* __restrict__ Y) {
    extern __shared__ __align__(16) uint32_t smu[];
    uint32_t* Qs = smu + SM_Q;
    uint32_t* Ks = smu + SM_K;
    uint32_t* Vs = smu + SM_V;
    uint32_t* Ps = smu + SM_P;

    const int tid = threadIdx.x;
    const int lane = tid & 31;
    const int warp = tid >> 5;
    const int g4 = lane >> 2;
    const int a4 = lane & 3;

    const int qtile = (gridDim.x - 1) - blockIdx.x;
    const int bh = blockIdx.y;
    const int b = bh >> 4, h = bh & 15;
    const int kv = h >> 2;

    const float* qbase = qkv + ((size_t)(b * TT + qtile * 128)) * N1 + h * DD;
#pragma unroll
    for (int i = 0; i < 16; i++) {
        int idx = tid + i * 256;
        int row = idx >> 5;
        int col = (idx & 31) * 4;
        float4 q = *(const float4*)(qbase + (size_t)row * N1 + col);
        uint4 t;
        t.x = f2tf32(q.x); t.y = f2tf32(q.y);
        t.z = f2tf32(q.z); t.w = f2tf32(q.w);
        *(uint4*)(Qs + row * QS_S + col) = t;
    }

    float oacc[16][4];
#pragma unroll
    for (int nt = 0; nt < 16; nt++)
#pragma unroll
        for (int r = 0; r < 4; r++) oacc[nt][r] = 0.f;
    float m0 = -1e30f, m1 = -1e30f, l0 = 0.f, l1 = 0.f;

    const float scale = 0.08838834764831845f;
    const float* kbase = Kg + ((size_t)(b * NKVH + kv) * TT) * DD;
    const float* vbase = Vg + ((size_t)(b * NKVH + kv) * TT) * DD;

    const int rloc = warp * 16 + g4;
    const int grow0 = qtile * 128 + rloc;
    const int grow1 = grow0 + 8;

    const int njt = 2 * qtile + 2;
    for (int jt = 0; jt < njt; jt++) {
        __syncthreads();
#pragma unroll
        for (int i = 0; i < 8; i++) {
            int idx = tid + i * 256;
            int tok = idx >> 5;
            int col = (idx & 31) * 4;
            const float4* kp = (const float4*)(kbase + (size_t)(jt * 64 + tok) * DD + col);
            const float4* vp = (const float4*)(vbase + (size_t)(jt * 64 + tok) * DD + col);
            *(uint4*)(Ks + tok * KS_S + col) = *(const uint4*)kp;
            *(uint4*)(Vs + tok * VS_S2 + col) = *(const uint4*)vp;
        }
        __syncthreads();

        float sacc[8][4];
#pragma unroll
        for (int nt = 0; nt < 8; nt++)
#pragma unroll
            for (int r = 0; r < 4; r++) sacc[nt][r] = 0.f;

#pragma unroll
        for (int kt = 0; kt < 16; kt++) {
            uint32_t af[4];
            int c = kt * 8 + a4;
            af[0] = Qs[rloc * QS_S + c];
            af[1] = Qs[(rloc + 8) * QS_S + c];
            af[2] = Qs[rloc * QS_S + c + 4];
            af[3] = Qs[(rloc + 8) * QS_S + c + 4];
#pragma unroll
            for (int nt = 0; nt < 8; nt++) {
                int n = nt * 8 + g4;
                mma_tf32(sacc[nt], af, Ks[n * KS_S + kt * 8 + a4],
                         Ks[n * KS_S + kt * 8 + a4 + 4]);
            }
        }

        if (jt >= 2 * qtile) {
#pragma unroll
            for (int nt = 0; nt < 8; nt++) {
                int gc = jt * 64 + nt * 8 + 2 * a4;
                sacc[nt][0] = (gc     > grow0) ? -1e30f : sacc[nt][0] * scale;
                sacc[nt][1] = (gc + 1 > grow0) ? -1e30f : sacc[nt][1] * scale;
                sacc[nt][2] = (gc     > grow1) ? -1e30f : sacc[nt][2] * scale;
                sacc[nt][3] = (gc + 1 > grow1) ? -1e30f : sacc[nt][3] * scale;
            }
        } else {
#pragma unroll
            for (int nt = 0; nt < 8; nt++)
#pragma unroll
                for (int r = 0; r < 4; r++) sacc[nt][r] *= scale;
        }

        float rm0 = -1e30f, rm1 = -1e30f;
#pragma unroll
        for (int nt = 0; nt < 8; nt++) {
            rm0 = fmaxf(rm0, fmaxf(sacc[nt][0], sacc[nt][1]));
            rm1 = fmaxf(rm1, fmaxf(sacc[nt][2], sacc[nt][3]));
        }
        rm0 = fmaxf(rm0, __shfl_xor_sync(0xffffffffu, rm0, 1));
        rm0 = fmaxf(rm0, __shfl_xor_sync(0xffffffffu, rm0, 2));
        rm1 = fmaxf(rm1, __shfl_xor_sync(0xffffffffu, rm1, 1));
        rm1 = fmaxf(rm1, __shfl_xor_sync(0xffffffffu, rm1, 2));

        float mn0 = fmaxf(m0, rm0), mn1 = fmaxf(m1, rm1);
        float corr0 = __expf(m0 - mn0), corr1 = __expf(m1 - mn1);
        m0 = mn0; m1 = mn1;

        float rs0 = 0.f, rs1 = 0.f;
#pragma unroll
        for (int nt = 0; nt < 8; nt++) {
            float p0 = __expf(sacc[nt][0] - mn0);
            float p1 = __expf(sacc[nt][1] - mn0);
            float p2 = __expf(sacc[nt][2] - mn1);
            float p3 = __expf(sacc[nt][3] - mn1);
            rs0 += p0 + p1; rs1 += p2 + p3;
            int cc = nt * 8 + 2 * a4;
            *(uint2*)(Ps + rloc * PS_S + cc) = make_uint2(f2tf32(p0), f2tf32(p1));
            *(uint2*)(Ps + (rloc + 8) * PS_S + cc) = make_uint2(f2tf32(p2), f2tf32(p3));
        }
        rs0 += __shfl_xor_sync(0xffffffffu, rs0, 1);
        rs0 += __shfl_xor_sync(0xffffffffu, rs0, 2);
        rs1 += __shfl_xor_sync(0xffffffffu, rs1, 1);
        rs1 += __shfl_xor_sync(0xffffffffu, rs1, 2);
        l0 = l0 * corr0 + rs0;
        l1 = l1 * corr1 + rs1;

#pragma unroll
        for (int nt = 0; nt < 16; nt++) {
            oacc[nt][0] *= corr0; oacc[nt][1] *= corr0;
            oacc[nt][2] *= corr1; oacc[nt][3] *= corr1;
        }
        __syncwarp();

#pragma unroll
        for (int kt = 0; kt < 8; kt++) {
            uint32_t af[4];
            int c = kt * 8 + a4;
            af[0] = Ps[rloc * PS_S + c];
            af[1] = Ps[(rloc + 8) * PS_S + c];
            af[2] = Ps[rloc * PS_S + c + 4];
            af[3] = Ps[(rloc + 8) * PS_S + c + 4];
#pragma unroll
            for (int nt = 0; nt < 16; nt++) {
                mma_tf32(oacc[nt], af,
                         Vs[(kt * 8 + a4) * VS_S2 + nt * 8 + g4],
                         Vs[(kt * 8 + a4 + 4) * VS_S2 + nt * 8 + g4]);
            }
        }
    }

    float inv0 = 1.f / l0, inv1 = 1.f / l1;
    int t0 = qtile * 128 + rloc;
    float* y0 = Y + ((size_t)(b * TT + t0)) * EE + h * DD;
    float* y1 = Y + ((size_t)(b * TT + t0 + 8)) * EE + h * DD;
#pragma unroll
    for (int nt = 0; nt < 16; nt++) {
        int cc = nt * 8 + 2 * a4;
        *(float2*)(y0 + cc) = make_float2(
            __uint_as_float(f2tf32(oacc[nt][0] * inv0)),
            __uint_as_float(f2tf32(oacc[nt][1] * inv0)));
        *(float2*)(y1 + cc) = make_float2(
            __uint_as_float(f2tf32(oacc[nt][2] * inv1)),
            __uint_as_float(f2tf32(oacc[nt][3] * inv1)));
    }
}

// ---------------------------------------------------------------------------
extern "C" void kernel_launch(void* const* d_in, const int* in_sizes, int n_in,
                              void* d_out, int out_size) {
    const float* x  = (const float*)d_in[0];
    const float* Wa = (const float*)d_in[1];
    const float* ba = (const float*)d_in[2];
    const float* Wp = (const float*)d_in[3];
    const float* fc = (const float*)d_in[4];
    const float* fs = (const float*)d_in[5];
    float* out = (float*)d_out;

    float *qkv, *kg, *vg, *yb, *xt, *wat, *wpt;
    cudaGetSymbolAddress((void**)&qkv, g_qkv);
    cudaGetSymbolAddress((void**)&kg, g_k);
    cudaGetSymbolAddress((void**)&vg, g_v);
    cudaGetSymbolAddress((void**)&yb, g_y);
    cudaGetSymbolAddress((void**)&xt, g_xt);
    cudaGetSymbolAddress((void**)&wat, g_wat);
    cudaGetSymbolAddress((void**)&wpt, g_wpt);

    // operand prep
    conv_tf32<<<(MM * EE / 4 + 255) / 256, 256>>>(x, xt, MM * EE / 4);
    transpose_tf32<<<dim3(N1 / 32, EE / 32), dim3(32, 8)>>>(Wa, wat, EE, N1);
    transpose_tf32<<<dim3(EE / 32, EE / 32), dim3(32, 8)>>>(Wp, wpt, EE, EE);

    cudaFuncSetAttribute(gemm_v4, cudaFuncAttributeMaxDynamicSharedMemorySize,
                         V4_SMEM);

    // 1) QKV GEMM (+bias) with fused RoPE epilogue for K/V tiles
    gemm_v4<<<dim3(N1 / 128, MM / 64), 128, V4_SMEM>>>(
        xt, wat, ba, qkv, MM, N1, EE, 1, fc, fs, kg, vg);

    // 2) attention (rope kernel eliminated)
    int smem_bytes = SM_TOT * (int)sizeof(uint32_t);
    cudaFuncSetAttribute(attn_tf32, cudaFuncAttributeMaxDynamicSharedMemorySize,
                         smem_bytes);
    attn_tf32<<<dim3(TT / 128, BB * HH), 256, smem_bytes>>>(qkv, kg, vg, yb);

    // 3) output projection
    gemm_v4<<<dim3(EE / 128, MM / 64), 128, V4_SMEM>>>(
        yb, wpt, nullptr, out, MM, EE, EE, 0, nullptr, nullptr, nullptr, nullptr);
}